// round 5
// baseline (speedup 1.0000x reference)
#include <cuda_runtime.h>
#include <math.h>

#define NA 48
#define NB 24
#define DIM 286
#define NBATCH 256
#define NMU 6
#define L5OFF 165

// Scratch (static device globals; no allocation)
__device__ float g_c[NA * NMU];                // cos-like per (x, mu)
__device__ float g_s[NA * NMU];                // sin-like per (x, mu)
__device__ float g_act;                        // normalize2mom constant for tanh
__device__ float g_part[48];                   // partials for activation integral
__device__ float g_Q[NBATCH * 36 * 4 * NB];    // Q forms [b][mn][c][y]

__constant__ int c_off[6] = {0, 1, 10, 35, 84, 165};

// fast exact-enough tanh: 1 - 2/(e^{2x}+1)   (rel err ~1e-6, robust at +-inf)
__device__ __forceinline__ float ftanh(float x) {
    float e = __expf(2.0f * x);
    return 1.0f - 2.0f / (e + 1.0f);
}

// ---------------------------------------------------------------------------
// ACT_CST integral: trapz of tanh(x)^2 * N(0,1) over [-12,12], 100001 pts
// ---------------------------------------------------------------------------
__global__ void act_kernel() {
    int tid = blockIdx.x * blockDim.x + threadIdx.x;  // 48*256 = 12288
    float sum = 0.f;
    for (int i = tid; i <= 100000; i += 12288) {
        float x = -12.f + (float)i * 2.4e-4f;
        float t = tanhf(x);
        float p = __expf(-0.5f * x * x);
        sum += t * t * p;
    }
    for (int o = 16; o; o >>= 1) sum += __shfl_down_sync(0xffffffffu, sum, o);
    __shared__ float ws[8];
    int w = threadIdx.x >> 5;
    if ((threadIdx.x & 31) == 0) ws[w] = sum;
    __syncthreads();
    if (threadIdx.x == 0) {
        float b = 0.f;
        for (int i = 0; i < 8; i++) b += ws[i];
        g_part[blockIdx.x] = b;
    }
}

// ---------------------------------------------------------------------------
// Prep: per-sector 2x2 alpha-rotation (c,s) from the l=5 block of D:
// Ra5[x] = D5[x,0,0] * D5[0,0,0]^T / 11  (Rb orthogonal, Ra(0)=I)
// ---------------------------------------------------------------------------
__global__ void prep_kernel(const float* __restrict__ D) {
    int t = threadIdx.x;
    if (t < NA * NMU) {
        int x = t / NMU, mu = t % NMU;
        int p0 = 5 - mu, p1 = 5 + mu;
        const float* X = D + (size_t)x * NB * NA * DIM + L5OFF;
        const float* Z = D + L5OFF;
        float a00 = 0.f, a01 = 0.f, a10 = 0.f, a11 = 0.f;
        for (int k = 0; k < 11; k++) {
            float xp0 = X[p0 * 11 + k], xp1 = X[p1 * 11 + k];
            float zp0 = Z[p0 * 11 + k], zp1 = Z[p1 * 11 + k];
            a00 += xp0 * zp0; a01 += xp0 * zp1;
            a10 += xp1 * zp0; a11 += xp1 * zp1;
        }
        const float inv11 = 1.f / 11.f;
        g_c[t] = 0.5f * (a00 + a11) * inv11;
        g_s[t] = 0.5f * (a01 - a10) * inv11;
    }
    if (t == 0) {
        float tot = 0.f;
        for (int i = 0; i < 48; i++) tot += g_part[i];
        float I = tot * 2.4e-4f * 0.3989422804014327f;
        g_act = 1.0f / sqrtf(I);
    }
}

// ---------------------------------------------------------------------------
// Main: one CTA per (batch b, beta index y). Produces Q forms into g_Q.
// (Round-3 structure; only the g_Q store layout changed to [b][mn][c][y].)
// ---------------------------------------------------------------------------
__global__ __launch_bounds__(256) void so3_main(const float* __restrict__ feat,
                                                const float* __restrict__ D,
                                                const float* __restrict__ qw) {
    const int b = blockIdx.x / NB;
    const int y = blockIdx.x % NB;
    const int t = threadIdx.x;

    __shared__ float sF[DIM];
    __shared__ float sB[DIM];
    __shared__ float4 strig4[NA * 3];      // [x]: (c0,s0,c1,s1)(c2,s2,c3,s3)(c4,s4,c5,s5)
    __shared__ float2 strigT[NMU][NA];     // transposed copy: [nu][z] -> (c,s)
    __shared__ float4 sP4[36];             // (P00,P01,P10,P11)
    __shared__ float2 sT2[NMU][NA];        // (t0,t1)
    __shared__ float sG[NA][NA + 1];
    __shared__ float2 sU2[NMU][NA + 1];    // (u0,u1)

    float* strig = (float*)strig4;

    for (int i = t; i < DIM; i += 256) {
        sF[i] = feat[b * DIM + i];
        sB[i] = D[(size_t)y * NA * DIM + i];  // D[0][y][0][i]
    }
    for (int i = t; i < NA * NMU; i += 256) {
        int x = i / NMU, mu = i % NMU;
        float c = g_c[i], s = g_s[i];
        strig[x * 12 + mu * 2 + 0] = c;
        strig[x * 12 + mu * 2 + 1] = s;
        strigT[mu][x] = make_float2(c, s);
    }
    __syncthreads();

    // --- P forms -----------------------------------------------------------
    if (t < 36) {
        int mu = t / 6, nu = t % 6;
        float P00 = 0.f, P01 = 0.f, P10 = 0.f, P11 = 0.f;
        int l0 = mu > nu ? mu : nu;
        for (int l = l0; l <= 5; l++) {
            int dl = 2 * l + 1, off = c_off[l];
            int r0 = l - mu, r1 = l + mu, q0 = l - nu, q1 = l + nu;
            float F00 = sF[off + r0 * dl + q0], F01 = sF[off + r0 * dl + q1];
            float F10 = sF[off + r1 * dl + q0], F11 = sF[off + r1 * dl + q1];
            float B00 = sB[off + r0 * dl + q0], B01 = sB[off + r0 * dl + q1];
            float B10 = sB[off + r1 * dl + q0], B11 = sB[off + r1 * dl + q1];
            if (mu == 0) { F10 = F11 = 0.f; B10 = B11 = 0.f; }
            if (nu == 0) { F01 = F11 = 0.f; B01 = B11 = 0.f; }
            P00 +=  F00 * B00 + F01 * B01 + F10 * B10 + F11 * B11;
            P01 += -F00 * B01 + F01 * B00 - F10 * B11 + F11 * B10;
            P10 +=  F00 * B10 + F01 * B11 - F10 * B00 - F11 * B01;
            P11 += -F00 * B11 + F01 * B10 + F10 * B01 - F11 * B00;
        }
        sP4[t] = make_float4(P00, P01, P10, P11);
    }
    __syncthreads();

    // --- T stage: contract nu with z-trig (conflict-free via strigT) ------
    for (int i = t; i < NMU * NA; i += 256) {
        int mu = i / NA, z = i % NA;
        float t0 = 0.f, t1 = 0.f;
#pragma unroll
        for (int nu = 0; nu < NMU; nu++) {
            float4 P = sP4[mu * 6 + nu];
            float2 cs = strigT[nu][z];
            t0 += P.x * cs.x + P.y * cs.y;
            t1 += P.z * cs.x + P.w * cs.y;
        }
        sT2[mu][z] = make_float2(t0, t1);
    }
    __syncthreads();

    // --- synthesis + activation (register-tiled 3x3 outer product) --------
    {
        const float inv_s = 1.f / sqrtf(286.f);
        const float actq = g_act * qw[y];
        int xt = t >> 4, zt = t & 15;
        int x0 = xt * 3, z0 = zt * 3;
        float a00 = 0.f, a01 = 0.f, a02 = 0.f;
        float a10 = 0.f, a11 = 0.f, a12 = 0.f;
        float a20 = 0.f, a21 = 0.f, a22 = 0.f;
#pragma unroll
        for (int mu = 0; mu < NMU; mu++) {
            float2 c0 = *(const float2*)(strig + (x0 + 0) * 12 + mu * 2);
            float2 c1 = *(const float2*)(strig + (x0 + 1) * 12 + mu * 2);
            float2 c2 = *(const float2*)(strig + (x0 + 2) * 12 + mu * 2);
            float2 T0 = sT2[mu][z0 + 0];
            float2 T1 = sT2[mu][z0 + 1];
            float2 T2 = sT2[mu][z0 + 2];
            a00 += c0.x * T0.x + c0.y * T0.y;
            a01 += c0.x * T1.x + c0.y * T1.y;
            a02 += c0.x * T2.x + c0.y * T2.y;
            a10 += c1.x * T0.x + c1.y * T0.y;
            a11 += c1.x * T1.x + c1.y * T1.y;
            a12 += c1.x * T2.x + c1.y * T2.y;
            a20 += c2.x * T0.x + c2.y * T0.y;
            a21 += c2.x * T1.x + c2.y * T1.y;
            a22 += c2.x * T2.x + c2.y * T2.y;
        }
        sG[x0 + 0][z0 + 0] = actq * ftanh(a00 * inv_s);
        sG[x0 + 0][z0 + 1] = actq * ftanh(a01 * inv_s);
        sG[x0 + 0][z0 + 2] = actq * ftanh(a02 * inv_s);
        sG[x0 + 1][z0 + 0] = actq * ftanh(a10 * inv_s);
        sG[x0 + 1][z0 + 1] = actq * ftanh(a11 * inv_s);
        sG[x0 + 1][z0 + 2] = actq * ftanh(a12 * inv_s);
        sG[x0 + 2][z0 + 0] = actq * ftanh(a20 * inv_s);
        sG[x0 + 2][z0 + 1] = actq * ftanh(a21 * inv_s);
        sG[x0 + 2][z0 + 2] = actq * ftanh(a22 * inv_s);
    }
    __syncthreads();

    // --- U stage: contract x with trig; 4 lanes split x, shuffle-reduce ---
    if (t < 192) {
        int z = t >> 2, xg = t & 3;
        float u0 = 0.f, u1 = 0.f, u2 = 0.f, u3 = 0.f, u4 = 0.f, u5 = 0.f;
        float u6 = 0.f, u7 = 0.f, u8 = 0.f, u9 = 0.f, u10 = 0.f, u11 = 0.f;
#pragma unroll
        for (int k = 0; k < 12; k++) {
            int x = xg * 12 + k;
            float g = sG[x][z];
            float4 ta = strig4[x * 3 + 0];
            float4 tb = strig4[x * 3 + 1];
            float4 tc = strig4[x * 3 + 2];
            u0 += ta.x * g;  u1 += ta.y * g;  u2 += ta.z * g;  u3 += ta.w * g;
            u4 += tb.x * g;  u5 += tb.y * g;  u6 += tb.z * g;  u7 += tb.w * g;
            u8 += tc.x * g;  u9 += tc.y * g;  u10 += tc.z * g; u11 += tc.w * g;
        }
#define RED(v) v += __shfl_xor_sync(0xffffffffu, v, 1); v += __shfl_xor_sync(0xffffffffu, v, 2)
        RED(u0); RED(u1); RED(u2); RED(u3); RED(u4); RED(u5);
        RED(u6); RED(u7); RED(u8); RED(u9); RED(u10); RED(u11);
#undef RED
        if (xg == 0) {
            sU2[0][z] = make_float2(u0, u1);
            sU2[1][z] = make_float2(u2, u3);
            sU2[2][z] = make_float2(u4, u5);
            sU2[3][z] = make_float2(u6, u7);
            sU2[4][z] = make_float2(u8, u9);
            sU2[5][z] = make_float2(u10, u11);
        }
    }
    __syncthreads();

    // --- Q forms + transposed store [b][mn][c][y] --------------------------
    if (t < 36) {
        int mu = t / 6, nu = t % 6;
        float Q00 = 0.f, Q01 = 0.f, Q10 = 0.f, Q11 = 0.f;
        for (int z = 0; z < NA; z++) {
            float2 u = sU2[mu][z];
            float2 cs = strigT[nu][z];
            Q00 += u.x * cs.x; Q01 += u.x * cs.y;
            Q10 += u.y * cs.x; Q11 += u.y * cs.y;
        }
        int base = ((b * 36 + t) * 4) * NB + y;
        g_Q[base + 0 * NB] = Q00;
        g_Q[base + 1 * NB] = Q01;
        g_Q[base + 2 * NB] = Q10;
        g_Q[base + 3 * NB] = Q11;
    }
}

// ---------------------------------------------------------------------------
// Scatter: pure-LDG, no smem. 576 threads/CTA: thread pair (adjacent lanes)
// splits the 24-y sum 12/12 and combines with one shfl_xor.
//   out(r,q) = sum_y Q00 B(r,q) + sq Q01 B(r,qb) + sr Q10 B(rb,q) + sr sq Q11 B(rb,qb)
// ---------------------------------------------------------------------------
__global__ __launch_bounds__(576) void scatter_kernel(const float* __restrict__ D,
                                                      float* __restrict__ out) {
    const int b = blockIdx.x;
    const int tid = threadIdx.x;
    int o = tid >> 1;              // output element 0..287
    const int h = tid & 1;         // y-half
    const bool valid = o < DIM;
    if (!valid) o = DIM - 1;       // clamp: keep lanes alive for full-mask shfl

    int l = 5;
    if (o < 165) l = 4;
    if (o < 84)  l = 3;
    if (o < 35)  l = 2;
    if (o < 10)  l = 1;
    if (o < 1)   l = 0;
    int off = c_off[l], dl = 2 * l + 1;
    int k = o - off;
    int r = k / dl, q = k - r * dl;
    int rb = 2 * l - r, qb = 2 * l - q;
    int mu = r < l ? l - r : r - l;
    int nu = q < l ? l - q : q - l;
    float sr_ = (r < l) ? 1.f : -1.f;
    float sq_ = (q > l) ? 1.f : -1.f;
    int i_rq = o;
    int i_rqb = off + r * dl + qb;
    int i_rbq = off + rb * dl + q;
    int i_rbqb = off + rb * dl + qb;

    const float* Qp = g_Q + ((size_t)(b * 36 + mu * 6 + nu)) * 4 * NB + h * 12;
    float A0 = 0.f, A1 = 0.f, A2 = 0.f, A3 = 0.f;
#pragma unroll
    for (int yv = 0; yv < 3; yv++) {
        float4 q0 = *(const float4*)(Qp + 0 * NB + yv * 4);
        float4 q1 = *(const float4*)(Qp + 1 * NB + yv * 4);
        float4 q2 = *(const float4*)(Qp + 2 * NB + yv * 4);
        float4 q3 = *(const float4*)(Qp + 3 * NB + yv * 4);
        int yb = h * 12 + yv * 4;
        const float* B0 = D + (size_t)(yb + 0) * NA * DIM;
        const float* B1 = D + (size_t)(yb + 1) * NA * DIM;
        const float* B2 = D + (size_t)(yb + 2) * NA * DIM;
        const float* B3 = D + (size_t)(yb + 3) * NA * DIM;
        A0 += q0.x * B0[i_rq]  + q0.y * B1[i_rq]  + q0.z * B2[i_rq]  + q0.w * B3[i_rq];
        A1 += q1.x * B0[i_rqb] + q1.y * B1[i_rqb] + q1.z * B2[i_rqb] + q1.w * B3[i_rqb];
        A2 += q2.x * B0[i_rbq] + q2.y * B1[i_rbq] + q2.z * B2[i_rbq] + q2.w * B3[i_rbq];
        A3 += q3.x * B0[i_rbqb]+ q3.y * B1[i_rbqb]+ q3.z * B2[i_rbqb]+ q3.w * B3[i_rbqb];
    }
    float acc = A0 + sq_ * A1 + sr_ * (A2 + sq_ * A3);
    acc += __shfl_xor_sync(0xffffffffu, acc, 1);
    if (valid && h == 0)
        out[(size_t)b * DIM + o] = sqrtf(286.f) * acc;
}

extern "C" void kernel_launch(void* const* d_in, const int* in_sizes, int n_in,
                              void* d_out, int out_size) {
    const float* feat = (const float*)d_in[0];  // [256, 286]
    const float* D    = (const float*)d_in[1];  // [48, 24, 48, 286]
    const float* qw   = (const float*)d_in[2];  // [24]
    float* out        = (float*)d_out;          // [256, 286]

    act_kernel<<<48, 256>>>();
    prep_kernel<<<1, 512>>>(D);
    so3_main<<<NBATCH * NB, 256>>>(feat, D, qw);
    scatter_kernel<<<NBATCH, 576>>>(D, out);
}

// round 6
// speedup vs baseline: 1.0199x; 1.0199x over previous
#include <cuda_runtime.h>
#include <math.h>

#define NA 48
#define NB 24
#define DIM 286
#define NBATCH 256
#define NMU 6
#define L5OFF 165

// Scratch (static device globals; no allocation)
__device__ float g_c[NA * NMU];                // cos-like per (x, mu)
__device__ float g_s[NA * NMU];                // sin-like per (x, mu)
__device__ float g_act;                        // normalize2mom constant for tanh
__device__ float g_part[48];                   // partials for activation integral
__device__ float g_Q[NBATCH * NB * 144];       // Q forms [b][y][mn*4+c]

__constant__ int c_off[6] = {0, 1, 10, 35, 84, 165};

// fast exact-enough tanh: 1 - 2/(e^{2x}+1)   (rel err ~1e-6, robust at +-inf)
__device__ __forceinline__ float ftanh(float x) {
    float e = __expf(2.0f * x);
    return 1.0f - 2.0f / (e + 1.0f);
}

// ---------------------------------------------------------------------------
// ACT_CST integral: trapz of tanh(x)^2 * N(0,1) over [-12,12], 100001 pts
// ---------------------------------------------------------------------------
__global__ void act_kernel() {
    int tid = blockIdx.x * blockDim.x + threadIdx.x;  // 48*256 = 12288
    float sum = 0.f;
    for (int i = tid; i <= 100000; i += 12288) {
        float x = -12.f + (float)i * 2.4e-4f;
        float t = tanhf(x);
        float p = __expf(-0.5f * x * x);
        sum += t * t * p;
    }
    for (int o = 16; o; o >>= 1) sum += __shfl_down_sync(0xffffffffu, sum, o);
    __shared__ float ws[8];
    int w = threadIdx.x >> 5;
    if ((threadIdx.x & 31) == 0) ws[w] = sum;
    __syncthreads();
    if (threadIdx.x == 0) {
        float b = 0.f;
        for (int i = 0; i < 8; i++) b += ws[i];
        g_part[blockIdx.x] = b;
    }
}

// ---------------------------------------------------------------------------
// Prep: per-sector 2x2 alpha-rotation (c,s) from the l=5 block of D:
// Ra5[x] = D5[x,0,0] * D5[0,0,0]^T / 11  (Rb orthogonal, Ra(0)=I)
// ---------------------------------------------------------------------------
__global__ void prep_kernel(const float* __restrict__ D) {
    int t = threadIdx.x;
    if (t < NA * NMU) {
        int x = t / NMU, mu = t % NMU;
        int p0 = 5 - mu, p1 = 5 + mu;
        const float* X = D + (size_t)x * NB * NA * DIM + L5OFF;
        const float* Z = D + L5OFF;
        float a00 = 0.f, a01 = 0.f, a10 = 0.f, a11 = 0.f;
        for (int k = 0; k < 11; k++) {
            float xp0 = X[p0 * 11 + k], xp1 = X[p1 * 11 + k];
            float zp0 = Z[p0 * 11 + k], zp1 = Z[p1 * 11 + k];
            a00 += xp0 * zp0; a01 += xp0 * zp1;
            a10 += xp1 * zp0; a11 += xp1 * zp1;
        }
        const float inv11 = 1.f / 11.f;
        g_c[t] = 0.5f * (a00 + a11) * inv11;
        g_s[t] = 0.5f * (a01 - a10) * inv11;
    }
    if (t == 0) {
        float tot = 0.f;
        for (int i = 0; i < 48; i++) tot += g_part[i];
        float I = tot * 2.4e-4f * 0.3989422804014327f;
        g_act = 1.0f / sqrtf(I);
    }
}

// ---------------------------------------------------------------------------
// Main: one CTA per (batch b, beta index y). Produces Q forms into g_Q.
// (Exact round-3 structure, coalesced float4 Q store.)
// ---------------------------------------------------------------------------
__global__ __launch_bounds__(256) void so3_main(const float* __restrict__ feat,
                                                const float* __restrict__ D,
                                                const float* __restrict__ qw) {
    const int b = blockIdx.x / NB;
    const int y = blockIdx.x % NB;
    const int t = threadIdx.x;

    __shared__ float sF[DIM];
    __shared__ float sB[DIM];
    __shared__ float4 strig4[NA * 3];      // [x]: (c0,s0,c1,s1)(c2,s2,c3,s3)(c4,s4,c5,s5)
    __shared__ float2 strigT[NMU][NA];     // transposed copy: [nu][z] -> (c,s)
    __shared__ float4 sP4[36];             // (P00,P01,P10,P11)
    __shared__ float2 sT2[NMU][NA];        // (t0,t1)
    __shared__ float sG[NA][NA + 1];
    __shared__ float2 sU2[NMU][NA + 1];    // (u0,u1)

    float* strig = (float*)strig4;

    for (int i = t; i < DIM; i += 256) {
        sF[i] = feat[b * DIM + i];
        sB[i] = D[(size_t)y * NA * DIM + i];  // D[0][y][0][i]
    }
    for (int i = t; i < NA * NMU; i += 256) {
        int x = i / NMU, mu = i % NMU;
        float c = g_c[i], s = g_s[i];
        strig[x * 12 + mu * 2 + 0] = c;
        strig[x * 12 + mu * 2 + 1] = s;
        strigT[mu][x] = make_float2(c, s);
    }
    __syncthreads();

    // --- P forms -----------------------------------------------------------
    if (t < 36) {
        int mu = t / 6, nu = t % 6;
        float P00 = 0.f, P01 = 0.f, P10 = 0.f, P11 = 0.f;
        int l0 = mu > nu ? mu : nu;
        for (int l = l0; l <= 5; l++) {
            int dl = 2 * l + 1, off = c_off[l];
            int r0 = l - mu, r1 = l + mu, q0 = l - nu, q1 = l + nu;
            float F00 = sF[off + r0 * dl + q0], F01 = sF[off + r0 * dl + q1];
            float F10 = sF[off + r1 * dl + q0], F11 = sF[off + r1 * dl + q1];
            float B00 = sB[off + r0 * dl + q0], B01 = sB[off + r0 * dl + q1];
            float B10 = sB[off + r1 * dl + q0], B11 = sB[off + r1 * dl + q1];
            if (mu == 0) { F10 = F11 = 0.f; B10 = B11 = 0.f; }
            if (nu == 0) { F01 = F11 = 0.f; B01 = B11 = 0.f; }
            P00 +=  F00 * B00 + F01 * B01 + F10 * B10 + F11 * B11;
            P01 += -F00 * B01 + F01 * B00 - F10 * B11 + F11 * B10;
            P10 +=  F00 * B10 + F01 * B11 - F10 * B00 - F11 * B01;
            P11 += -F00 * B11 + F01 * B10 + F10 * B01 - F11 * B00;
        }
        sP4[t] = make_float4(P00, P01, P10, P11);
    }
    __syncthreads();

    // --- T stage: contract nu with z-trig (conflict-free via strigT) ------
    for (int i = t; i < NMU * NA; i += 256) {
        int mu = i / NA, z = i % NA;
        float t0 = 0.f, t1 = 0.f;
#pragma unroll
        for (int nu = 0; nu < NMU; nu++) {
            float4 P = sP4[mu * 6 + nu];
            float2 cs = strigT[nu][z];
            t0 += P.x * cs.x + P.y * cs.y;
            t1 += P.z * cs.x + P.w * cs.y;
        }
        sT2[mu][z] = make_float2(t0, t1);
    }
    __syncthreads();

    // --- synthesis + activation (register-tiled 3x3 outer product) --------
    {
        const float inv_s = 1.f / sqrtf(286.f);
        const float actq = g_act * qw[y];
        int xt = t >> 4, zt = t & 15;
        int x0 = xt * 3, z0 = zt * 3;
        float a00 = 0.f, a01 = 0.f, a02 = 0.f;
        float a10 = 0.f, a11 = 0.f, a12 = 0.f;
        float a20 = 0.f, a21 = 0.f, a22 = 0.f;
#pragma unroll
        for (int mu = 0; mu < NMU; mu++) {
            float2 c0 = *(const float2*)(strig + (x0 + 0) * 12 + mu * 2);
            float2 c1 = *(const float2*)(strig + (x0 + 1) * 12 + mu * 2);
            float2 c2 = *(const float2*)(strig + (x0 + 2) * 12 + mu * 2);
            float2 T0 = sT2[mu][z0 + 0];
            float2 T1 = sT2[mu][z0 + 1];
            float2 T2 = sT2[mu][z0 + 2];
            a00 += c0.x * T0.x + c0.y * T0.y;
            a01 += c0.x * T1.x + c0.y * T1.y;
            a02 += c0.x * T2.x + c0.y * T2.y;
            a10 += c1.x * T0.x + c1.y * T0.y;
            a11 += c1.x * T1.x + c1.y * T1.y;
            a12 += c1.x * T2.x + c1.y * T2.y;
            a20 += c2.x * T0.x + c2.y * T0.y;
            a21 += c2.x * T1.x + c2.y * T1.y;
            a22 += c2.x * T2.x + c2.y * T2.y;
        }
        sG[x0 + 0][z0 + 0] = actq * ftanh(a00 * inv_s);
        sG[x0 + 0][z0 + 1] = actq * ftanh(a01 * inv_s);
        sG[x0 + 0][z0 + 2] = actq * ftanh(a02 * inv_s);
        sG[x0 + 1][z0 + 0] = actq * ftanh(a10 * inv_s);
        sG[x0 + 1][z0 + 1] = actq * ftanh(a11 * inv_s);
        sG[x0 + 1][z0 + 2] = actq * ftanh(a12 * inv_s);
        sG[x0 + 2][z0 + 0] = actq * ftanh(a20 * inv_s);
        sG[x0 + 2][z0 + 1] = actq * ftanh(a21 * inv_s);
        sG[x0 + 2][z0 + 2] = actq * ftanh(a22 * inv_s);
    }
    __syncthreads();

    // --- U stage: contract x with trig; 4 lanes split x, shuffle-reduce ---
    if (t < 192) {
        int z = t >> 2, xg = t & 3;
        float u0 = 0.f, u1 = 0.f, u2 = 0.f, u3 = 0.f, u4 = 0.f, u5 = 0.f;
        float u6 = 0.f, u7 = 0.f, u8 = 0.f, u9 = 0.f, u10 = 0.f, u11 = 0.f;
#pragma unroll
        for (int k = 0; k < 12; k++) {
            int x = xg * 12 + k;
            float g = sG[x][z];
            float4 ta = strig4[x * 3 + 0];
            float4 tb = strig4[x * 3 + 1];
            float4 tc = strig4[x * 3 + 2];
            u0 += ta.x * g;  u1 += ta.y * g;  u2 += ta.z * g;  u3 += ta.w * g;
            u4 += tb.x * g;  u5 += tb.y * g;  u6 += tb.z * g;  u7 += tb.w * g;
            u8 += tc.x * g;  u9 += tc.y * g;  u10 += tc.z * g; u11 += tc.w * g;
        }
#define RED(v) v += __shfl_xor_sync(0xffffffffu, v, 1); v += __shfl_xor_sync(0xffffffffu, v, 2)
        RED(u0); RED(u1); RED(u2); RED(u3); RED(u4); RED(u5);
        RED(u6); RED(u7); RED(u8); RED(u9); RED(u10); RED(u11);
#undef RED
        if (xg == 0) {
            sU2[0][z] = make_float2(u0, u1);
            sU2[1][z] = make_float2(u2, u3);
            sU2[2][z] = make_float2(u4, u5);
            sU2[3][z] = make_float2(u6, u7);
            sU2[4][z] = make_float2(u8, u9);
            sU2[5][z] = make_float2(u10, u11);
        }
    }
    __syncthreads();

    // --- Q forms + coalesced float4 store [b][y][mn*4] ---------------------
    if (t < 36) {
        int mu = t / 6, nu = t % 6;
        float Q00 = 0.f, Q01 = 0.f, Q10 = 0.f, Q11 = 0.f;
        for (int z = 0; z < NA; z++) {
            float2 u = sU2[mu][z];
            float2 cs = strigT[nu][z];
            Q00 += u.x * cs.x; Q01 += u.x * cs.y;
            Q10 += u.y * cs.x; Q11 += u.y * cs.y;
        }
        *(float4*)(g_Q + ((size_t)(b * NB + y)) * 144 + t * 4) =
            make_float4(Q00, Q01, Q10, Q11);
    }
}

// ---------------------------------------------------------------------------
// Scatter: pure-LDG, no smem. grid (256 b, 2 o-halves) x 576 threads.
// 4 adjacent lanes split the 24-y sum (6 y each), combine with 2 shfl_xor.
// Q layout [b][y][mn*4]: one LDG.128 per y fetches all 4 components.
//   out(r,q) = sum_y Q00 B(r,q) + sq Q01 B(r,qb) + sr Q10 B(rb,q) + sr sq Q11 B(rb,qb)
// ---------------------------------------------------------------------------
__global__ __launch_bounds__(576) void scatter_kernel(const float* __restrict__ D,
                                                      float* __restrict__ out) {
    const int b = blockIdx.x;
    const int tid = threadIdx.x;
    int o = blockIdx.y * 144 + (tid >> 2);   // output element
    const int h = tid & 3;                   // y-quarter
    const bool valid = o < DIM;
    if (!valid) o = DIM - 1;                 // clamp: keep lanes alive for shfl

    int l = 5;
    if (o < 165) l = 4;
    if (o < 84)  l = 3;
    if (o < 35)  l = 2;
    if (o < 10)  l = 1;
    if (o < 1)   l = 0;
    int off = c_off[l], dl = 2 * l + 1;
    int k = o - off;
    int r = k / dl, q = k - r * dl;
    int rb = 2 * l - r, qb = 2 * l - q;
    int mu = r < l ? l - r : r - l;
    int nu = q < l ? l - q : q - l;
    float sr_ = (r < l) ? 1.f : -1.f;
    float sq_ = (q > l) ? 1.f : -1.f;
    int i_rq = o;
    int i_rqb = off + r * dl + qb;
    int i_rbq = off + rb * dl + q;
    int i_rbqb = off + rb * dl + qb;
    int mn4 = (mu * 6 + nu) * 4;

    float A0 = 0.f, A1 = 0.f, A2 = 0.f, A3 = 0.f;
#pragma unroll
    for (int yv = 0; yv < 6; yv++) {
        int y = h * 6 + yv;
        float4 Q = *(const float4*)(g_Q + ((size_t)(b * NB + y)) * 144 + mn4);
        const float* By = D + (size_t)y * NA * DIM;
        A0 += Q.x * By[i_rq];
        A1 += Q.y * By[i_rqb];
        A2 += Q.z * By[i_rbq];
        A3 += Q.w * By[i_rbqb];
    }
    float acc = A0 + sq_ * A1 + sr_ * (A2 + sq_ * A3);
    acc += __shfl_xor_sync(0xffffffffu, acc, 1);
    acc += __shfl_xor_sync(0xffffffffu, acc, 2);
    if (valid && h == 0)
        out[(size_t)b * DIM + o] = sqrtf(286.f) * acc;
}

extern "C" void kernel_launch(void* const* d_in, const int* in_sizes, int n_in,
                              void* d_out, int out_size) {
    const float* feat = (const float*)d_in[0];  // [256, 286]
    const float* D    = (const float*)d_in[1];  // [48, 24, 48, 286]
    const float* qw   = (const float*)d_in[2];  // [24]
    float* out        = (float*)d_out;          // [256, 286]

    act_kernel<<<48, 256>>>();
    prep_kernel<<<1, 512>>>(D);
    so3_main<<<NBATCH * NB, 256>>>(feat, D, qw);
    scatter_kernel<<<dim3(NBATCH, 2), 576>>>(D, out);
}

// round 7
// speedup vs baseline: 1.4959x; 1.4667x over previous
#include <cuda_runtime.h>
#include <math.h>

#define NA 48
#define NB 24
#define DIM 286
#define NBATCH 256
#define NMU 6
#define L5OFF 165

// Scratch (static device globals; no allocation)
__device__ float g_c[NA * NMU];                // cos-like per (x, mu)
__device__ float g_s[NA * NMU];                // sin-like per (x, mu)
__device__ float g_act;                        // normalize2mom constant for tanh
__device__ float g_part[48];                   // partials for activation integral
__device__ float g_Q[NBATCH * NB * 144];       // Q forms [b][y][mn*4+c]

__constant__ int c_off[6] = {0, 1, 10, 35, 84, 165};

// fast exact-enough tanh: 1 - 2/(e^{2x}+1)   (rel err ~1e-6, robust at +-inf)
__device__ __forceinline__ float ftanh(float x) {
    float e = __expf(2.0f * x);
    return 1.0f - 2.0f / (e + 1.0f);
}

// ---------------------------------------------------------------------------
// ACT_CST integral: trapz of tanh(x)^2 * N(0,1) over [-12,12], 100001 pts
// ---------------------------------------------------------------------------
__global__ void act_kernel() {
    int tid = blockIdx.x * blockDim.x + threadIdx.x;  // 48*256 = 12288
    float sum = 0.f;
    for (int i = tid; i <= 100000; i += 12288) {
        float x = -12.f + (float)i * 2.4e-4f;
        float t = tanhf(x);
        float p = __expf(-0.5f * x * x);
        sum += t * t * p;
    }
    for (int o = 16; o; o >>= 1) sum += __shfl_down_sync(0xffffffffu, sum, o);
    __shared__ float ws[8];
    int w = threadIdx.x >> 5;
    if ((threadIdx.x & 31) == 0) ws[w] = sum;
    __syncthreads();
    if (threadIdx.x == 0) {
        float b = 0.f;
        for (int i = 0; i < 8; i++) b += ws[i];
        g_part[blockIdx.x] = b;
    }
}

// ---------------------------------------------------------------------------
// Prep: per-sector 2x2 alpha-rotation (c,s) from the l=5 block of D:
// Ra5[x] = D5[x,0,0] * D5[0,0,0]^T / 11  (Rb orthogonal, Ra(0)=I)
// ---------------------------------------------------------------------------
__global__ void prep_kernel(const float* __restrict__ D) {
    int t = threadIdx.x;
    if (t < NA * NMU) {
        int x = t / NMU, mu = t % NMU;
        int p0 = 5 - mu, p1 = 5 + mu;
        const float* X = D + (size_t)x * NB * NA * DIM + L5OFF;
        const float* Z = D + L5OFF;
        float a00 = 0.f, a01 = 0.f, a10 = 0.f, a11 = 0.f;
        for (int k = 0; k < 11; k++) {
            float xp0 = X[p0 * 11 + k], xp1 = X[p1 * 11 + k];
            float zp0 = Z[p0 * 11 + k], zp1 = Z[p1 * 11 + k];
            a00 += xp0 * zp0; a01 += xp0 * zp1;
            a10 += xp1 * zp0; a11 += xp1 * zp1;
        }
        const float inv11 = 1.f / 11.f;
        g_c[t] = 0.5f * (a00 + a11) * inv11;
        g_s[t] = 0.5f * (a01 - a10) * inv11;
    }
    if (t == 0) {
        float tot = 0.f;
        for (int i = 0; i < 48; i++) tot += g_part[i];
        float I = tot * 2.4e-4f * 0.3989422804014327f;
        g_act = 1.0f / sqrtf(I);
    }
}

// ---------------------------------------------------------------------------
// Main (warp-autonomous): grid (b, ys) x 128 threads. Warp w handles
// y = ys*4 + w end-to-end: P -> T(regs) -> fused synth+tanh+U -> Q.
// No CTA barriers after the initial load; G never materialized.
// Each lane owns z0=lane and (lanes 0-15) z1=32+lane.
// ---------------------------------------------------------------------------
__global__ __launch_bounds__(128) void so3_main(const float* __restrict__ feat,
                                                const float* __restrict__ D,
                                                const float* __restrict__ qw) {
    const int b = blockIdx.x;
    const int t = threadIdx.x;
    const int w = t >> 5;
    const int lane = t & 31;
    const int y = blockIdx.y * 4 + w;

    __shared__ float sF[DIM];
    __shared__ __align__(16) float strigX[NA][12];   // x-major trig, broadcast reads
    __shared__ float2 strigT[NMU][NA + 1];           // [mu][z], padded row (392B)
    __shared__ float sB[4][DIM + 2];                 // per-warp B slice
    __shared__ float4 sP4[4][36];                    // per-warp P forms
    __shared__ float2 sU[4][NMU][NA + 1];            // per-warp U, padded row

    for (int i = t; i < DIM; i += 128) sF[i] = feat[b * DIM + i];
    for (int i = t; i < NA * NMU; i += 128) {
        int x = i / NMU, mu = i % NMU;
        float c = g_c[i], s = g_s[i];
        strigX[x][mu * 2 + 0] = c;
        strigX[x][mu * 2 + 1] = s;
        strigT[mu][x] = make_float2(c, s);
    }
    {
        const float* Dy = D + (size_t)y * NA * DIM;
        for (int i = lane; i < DIM; i += 32) sB[w][i] = Dy[i];
    }
    __syncthreads();

    // --- P forms (36 over 32 lanes; lanes 0-3 take a second form) ----------
#pragma unroll
    for (int rep = 0; rep < 2; rep++) {
        int f = lane + rep * 32;
        if (f < 36) {
            int mu = f / 6, nu = f % 6;
            float P00 = 0.f, P01 = 0.f, P10 = 0.f, P11 = 0.f;
            int l0 = mu > nu ? mu : nu;
            for (int l = l0; l <= 5; l++) {
                int dl = 2 * l + 1, off = c_off[l];
                int r0 = l - mu, r1 = l + mu, q0 = l - nu, q1 = l + nu;
                float F00 = sF[off + r0 * dl + q0], F01 = sF[off + r0 * dl + q1];
                float F10 = sF[off + r1 * dl + q0], F11 = sF[off + r1 * dl + q1];
                float B00 = sB[w][off + r0 * dl + q0], B01 = sB[w][off + r0 * dl + q1];
                float B10 = sB[w][off + r1 * dl + q0], B11 = sB[w][off + r1 * dl + q1];
                if (mu == 0) { F10 = F11 = 0.f; B10 = B11 = 0.f; }
                if (nu == 0) { F01 = F11 = 0.f; B01 = B11 = 0.f; }
                P00 +=  F00 * B00 + F01 * B01 + F10 * B10 + F11 * B11;
                P01 += -F00 * B01 + F01 * B00 - F10 * B11 + F11 * B10;
                P10 +=  F00 * B10 + F01 * B11 - F10 * B00 - F11 * B01;
                P11 += -F00 * B11 + F01 * B10 + F10 * B01 - F11 * B00;
            }
            sP4[w][f] = make_float4(P00, P01, P10, P11);
        }
    }
    __syncwarp();

    // --- T stage, fully in registers (z0=lane; z1=32+(lane&15)) ------------
    const int z0 = lane;
    const int z1 = 32 + (lane & 15);
    float T0a[6] = {}, T1a[6] = {}, T0b[6] = {}, T1b[6] = {};
#pragma unroll
    for (int nu = 0; nu < 6; nu++) {
        float2 ca = strigT[nu][z0];
        float2 cb = strigT[nu][z1];
#pragma unroll
        for (int mu = 0; mu < 6; mu++) {
            float4 P = sP4[w][mu * 6 + nu];
            T0a[mu] += P.x * ca.x + P.y * ca.y;
            T1a[mu] += P.z * ca.x + P.w * ca.y;
            T0b[mu] += P.x * cb.x + P.y * cb.y;
            T1b[mu] += P.z * cb.x + P.w * cb.y;
        }
    }

    // --- fused synthesis + activation + U accumulation ---------------------
    const float inv_s = 1.f / sqrtf(286.f);
    const float actq = g_act * qw[y];
    float U0[12] = {}, U1[12] = {};
#pragma unroll 4
    for (int x = 0; x < NA; x++) {
        float4 ta = *(const float4*)&strigX[x][0];
        float4 tb = *(const float4*)&strigX[x][4];
        float4 tc = *(const float4*)&strigX[x][8];
        float ga = ta.x * T0a[0] + ta.y * T1a[0] + ta.z * T0a[1] + ta.w * T1a[1]
                 + tb.x * T0a[2] + tb.y * T1a[2] + tb.z * T0a[3] + tb.w * T1a[3]
                 + tc.x * T0a[4] + tc.y * T1a[4] + tc.z * T0a[5] + tc.w * T1a[5];
        float gb = ta.x * T0b[0] + ta.y * T1b[0] + ta.z * T0b[1] + ta.w * T1b[1]
                 + tb.x * T0b[2] + tb.y * T1b[2] + tb.z * T0b[3] + tb.w * T1b[3]
                 + tc.x * T0b[4] + tc.y * T1b[4] + tc.z * T0b[5] + tc.w * T1b[5];
        float ha = actq * ftanh(ga * inv_s);
        float hb = actq * ftanh(gb * inv_s);
        U0[0] += ta.x * ha;  U0[1] += ta.y * ha;  U0[2]  += ta.z * ha;  U0[3]  += ta.w * ha;
        U0[4] += tb.x * ha;  U0[5] += tb.y * ha;  U0[6]  += tb.z * ha;  U0[7]  += tb.w * ha;
        U0[8] += tc.x * ha;  U0[9] += tc.y * ha;  U0[10] += tc.z * ha;  U0[11] += tc.w * ha;
        U1[0] += ta.x * hb;  U1[1] += ta.y * hb;  U1[2]  += ta.z * hb;  U1[3]  += ta.w * hb;
        U1[4] += tb.x * hb;  U1[5] += tb.y * hb;  U1[6]  += tb.z * hb;  U1[7]  += tb.w * hb;
        U1[8] += tc.x * hb;  U1[9] += tc.y * hb;  U1[10] += tc.z * hb;  U1[11] += tc.w * hb;
    }
#pragma unroll
    for (int mu = 0; mu < 6; mu++)
        sU[w][mu][z0] = make_float2(U0[2 * mu], U0[2 * mu + 1]);
    if (lane < 16) {
#pragma unroll
        for (int mu = 0; mu < 6; mu++)
            sU[w][mu][z1] = make_float2(U1[2 * mu], U1[2 * mu + 1]);
    }
    __syncwarp();

    // --- Q forms + coalesced float4 store [b][y][mn*4] ----------------------
#pragma unroll
    for (int rep = 0; rep < 2; rep++) {
        int f = lane + rep * 32;
        bool v = f < 36;
        int ff = v ? f : 35;
        int mu = ff / 6, nu = ff % 6;
        float Q00 = 0.f, Q01 = 0.f, Q10 = 0.f, Q11 = 0.f;
        for (int z = 0; z < NA; z++) {
            float2 u = sU[w][mu][z];
            float2 cs = strigT[nu][z];
            Q00 += u.x * cs.x; Q01 += u.x * cs.y;
            Q10 += u.y * cs.x; Q11 += u.y * cs.y;
        }
        if (v)
            *(float4*)(g_Q + ((size_t)(b * NB + y)) * 144 + f * 4) =
                make_float4(Q00, Q01, Q10, Q11);
    }
}

// ---------------------------------------------------------------------------
// Scatter: pure-LDG, no smem. grid (256 b, 2 o-halves) x 576 threads.
// 4 adjacent lanes split the 24-y sum (6 y each), combine with 2 shfl_xor.
// launch_bounds(576,3) lifts reg-limited occupancy 2->3 blocks/SM.
// ---------------------------------------------------------------------------
__global__ __launch_bounds__(576, 3) void scatter_kernel(const float* __restrict__ D,
                                                         float* __restrict__ out) {
    const int b = blockIdx.x;
    const int tid = threadIdx.x;
    int o = blockIdx.y * 144 + (tid >> 2);   // output element
    const int h = tid & 3;                   // y-quarter
    const bool valid = o < DIM;
    if (!valid) o = DIM - 1;                 // clamp: keep lanes alive for shfl

    int l = 5;
    if (o < 165) l = 4;
    if (o < 84)  l = 3;
    if (o < 35)  l = 2;
    if (o < 10)  l = 1;
    if (o < 1)   l = 0;
    int off = c_off[l], dl = 2 * l + 1;
    int k = o - off;
    int r = k / dl, q = k - r * dl;
    int rb = 2 * l - r, qb = 2 * l - q;
    int mu = r < l ? l - r : r - l;
    int nu = q < l ? l - q : q - l;
    float sr_ = (r < l) ? 1.f : -1.f;
    float sq_ = (q > l) ? 1.f : -1.f;
    int i_rq = o;
    int i_rqb = off + r * dl + qb;
    int i_rbq = off + rb * dl + q;
    int i_rbqb = off + rb * dl + qb;
    int mn4 = (mu * 6 + nu) * 4;

    float A0 = 0.f, A1 = 0.f, A2 = 0.f, A3 = 0.f;
#pragma unroll
    for (int yv = 0; yv < 6; yv++) {
        int y = h * 6 + yv;
        float4 Q = *(const float4*)(g_Q + ((size_t)(b * NB + y)) * 144 + mn4);
        const float* By = D + (size_t)y * NA * DIM;
        A0 += Q.x * By[i_rq];
        A1 += Q.y * By[i_rqb];
        A2 += Q.z * By[i_rbq];
        A3 += Q.w * By[i_rbqb];
    }
    float acc = A0 + sq_ * A1 + sr_ * (A2 + sq_ * A3);
    acc += __shfl_xor_sync(0xffffffffu, acc, 1);
    acc += __shfl_xor_sync(0xffffffffu, acc, 2);
    if (valid && h == 0)
        out[(size_t)b * DIM + o] = sqrtf(286.f) * acc;
}

extern "C" void kernel_launch(void* const* d_in, const int* in_sizes, int n_in,
                              void* d_out, int out_size) {
    const float* feat = (const float*)d_in[0];  // [256, 286]
    const float* D    = (const float*)d_in[1];  // [48, 24, 48, 286]
    const float* qw   = (const float*)d_in[2];  // [24]
    float* out        = (float*)d_out;          // [256, 286]

    act_kernel<<<48, 256>>>();
    prep_kernel<<<1, 512>>>(D);
    so3_main<<<dim3(NBATCH, 6), 128>>>(feat, D, qw);
    scatter_kernel<<<dim3(NBATCH, 2), 576>>>(D, out);
}

// round 8
// speedup vs baseline: 1.5467x; 1.0340x over previous
#include <cuda_runtime.h>
#include <math.h>

#define NA 48
#define NB 24
#define DIM 286
#define NBATCH 256
#define NMU 6
#define L5OFF 165

typedef unsigned long long u64;

// f32x2 packed helpers (FFMA2 — PTX-only on sm_103a)
__device__ __forceinline__ u64 pack2(float lo, float hi) {
    u64 r; asm("mov.b64 %0, {%1, %2};" : "=l"(r) : "f"(lo), "f"(hi)); return r;
}
__device__ __forceinline__ void unpack2(u64 v, float& lo, float& hi) {
    asm("mov.b64 {%0, %1}, %2;" : "=f"(lo), "=f"(hi) : "l"(v));
}
__device__ __forceinline__ u64 fma2(u64 a, u64 b, u64 c) {
    u64 r; asm("fma.rn.f32x2 %0, %1, %2, %3;" : "=l"(r) : "l"(a), "l"(b), "l"(c)); return r;
}

// Scratch (static device globals; no allocation)
__device__ float g_c[NA * NMU];                // cos-like per (x, mu)
__device__ float g_s[NA * NMU];                // sin-like per (x, mu)
__device__ float g_act;                        // normalize2mom constant for tanh
__device__ float g_part[48];                   // partials for activation integral
__device__ float g_Q[NBATCH * NB * 144];       // Q forms [b][y][mn*4+c]

__constant__ int c_off[6] = {0, 1, 10, 35, 84, 165};

// fast exact-enough tanh: 1 - 2/(e^{2x}+1)   (rel err ~1e-6, robust at +-inf)
__device__ __forceinline__ float ftanh(float x) {
    float e = __expf(2.0f * x);
    return 1.0f - 2.0f / (e + 1.0f);
}

// ---------------------------------------------------------------------------
// ACT_CST integral: trapz of tanh(x)^2 * N(0,1) over [-12,12], 100001 pts
// ---------------------------------------------------------------------------
__global__ void act_kernel() {
    int tid = blockIdx.x * blockDim.x + threadIdx.x;  // 48*256 = 12288
    float sum = 0.f;
    for (int i = tid; i <= 100000; i += 12288) {
        float x = -12.f + (float)i * 2.4e-4f;
        float t = tanhf(x);
        float p = __expf(-0.5f * x * x);
        sum += t * t * p;
    }
    for (int o = 16; o; o >>= 1) sum += __shfl_down_sync(0xffffffffu, sum, o);
    __shared__ float ws[8];
    int w = threadIdx.x >> 5;
    if ((threadIdx.x & 31) == 0) ws[w] = sum;
    __syncthreads();
    if (threadIdx.x == 0) {
        float b = 0.f;
        for (int i = 0; i < 8; i++) b += ws[i];
        g_part[blockIdx.x] = b;
    }
}

// ---------------------------------------------------------------------------
// Prep: per-sector 2x2 alpha-rotation (c,s) from the l=5 block of D:
// Ra5[x] = D5[x,0,0] * D5[0,0,0]^T / 11  (Rb orthogonal, Ra(0)=I)
// ---------------------------------------------------------------------------
__global__ void prep_kernel(const float* __restrict__ D) {
    int t = threadIdx.x;
    if (t < NA * NMU) {
        int x = t / NMU, mu = t % NMU;
        int p0 = 5 - mu, p1 = 5 + mu;
        const float* X = D + (size_t)x * NB * NA * DIM + L5OFF;
        const float* Z = D + L5OFF;
        float a00 = 0.f, a01 = 0.f, a10 = 0.f, a11 = 0.f;
        for (int k = 0; k < 11; k++) {
            float xp0 = X[p0 * 11 + k], xp1 = X[p1 * 11 + k];
            float zp0 = Z[p0 * 11 + k], zp1 = Z[p1 * 11 + k];
            a00 += xp0 * zp0; a01 += xp0 * zp1;
            a10 += xp1 * zp0; a11 += xp1 * zp1;
        }
        const float inv11 = 1.f / 11.f;
        g_c[t] = 0.5f * (a00 + a11) * inv11;
        g_s[t] = 0.5f * (a01 - a10) * inv11;
    }
    if (t == 0) {
        float tot = 0.f;
        for (int i = 0; i < 48; i++) tot += g_part[i];
        float I = tot * 2.4e-4f * 0.3989422804014327f;
        g_act = 1.0f / sqrtf(I);
    }
}

// ---------------------------------------------------------------------------
// Main (warp-autonomous, f32x2): grid (b, ys) x 128 threads. Warp w handles
// y = ys*4 + w end-to-end: P -> T(packed regs) -> fused synth+tanh+U -> Q.
// Lane owns z0=lane and z1=32+(lane&15); (z0,z1) pairs ride in f32x2 lanes.
// ---------------------------------------------------------------------------
__global__ __launch_bounds__(128) void so3_main(const float* __restrict__ feat,
                                                const float* __restrict__ D,
                                                const float* __restrict__ qw) {
    const int b = blockIdx.x;
    const int t = threadIdx.x;
    const int w = t >> 5;
    const int lane = t & 31;
    const int y = blockIdx.y * 4 + w;

    __shared__ float sF[DIM];
    __shared__ __align__(16) u64 strigX2[NA][12];    // [x]: (c0,c0)(s0,s0)...(s5,s5)
    __shared__ float2 strigT[NMU][NA + 1];           // [mu][z], padded row
    __shared__ float sB[4][DIM + 2];                 // per-warp B slice
    __shared__ float4 sP4[4][36];                    // per-warp P forms
    __shared__ float2 sU[4][NMU][NA + 1];            // per-warp U, padded row

    for (int i = t; i < DIM; i += 128) sF[i] = feat[b * DIM + i];
    for (int i = t; i < NA * NMU; i += 128) {
        int x = i / NMU, mu = i % NMU;
        float c = g_c[i], s = g_s[i];
        strigX2[x][mu * 2 + 0] = pack2(c, c);
        strigX2[x][mu * 2 + 1] = pack2(s, s);
        strigT[mu][x] = make_float2(c, s);
    }
    {
        const float* Dy = D + (size_t)y * NA * DIM;
        for (int i = lane; i < DIM; i += 32) sB[w][i] = Dy[i];
    }
    __syncthreads();

    // --- P forms (36 over 32 lanes; lanes 0-3 take a second form) ----------
#pragma unroll
    for (int rep = 0; rep < 2; rep++) {
        int f = lane + rep * 32;
        if (f < 36) {
            int mu = f / 6, nu = f % 6;
            float P00 = 0.f, P01 = 0.f, P10 = 0.f, P11 = 0.f;
            int l0 = mu > nu ? mu : nu;
            for (int l = l0; l <= 5; l++) {
                int dl = 2 * l + 1, off = c_off[l];
                int r0 = l - mu, r1 = l + mu, q0 = l - nu, q1 = l + nu;
                float F00 = sF[off + r0 * dl + q0], F01 = sF[off + r0 * dl + q1];
                float F10 = sF[off + r1 * dl + q0], F11 = sF[off + r1 * dl + q1];
                float B00 = sB[w][off + r0 * dl + q0], B01 = sB[w][off + r0 * dl + q1];
                float B10 = sB[w][off + r1 * dl + q0], B11 = sB[w][off + r1 * dl + q1];
                if (mu == 0) { F10 = F11 = 0.f; B10 = B11 = 0.f; }
                if (nu == 0) { F01 = F11 = 0.f; B01 = B11 = 0.f; }
                P00 +=  F00 * B00 + F01 * B01 + F10 * B10 + F11 * B11;
                P01 += -F00 * B01 + F01 * B00 - F10 * B11 + F11 * B10;
                P10 +=  F00 * B10 + F01 * B11 - F10 * B00 - F11 * B01;
                P11 += -F00 * B11 + F01 * B10 + F10 * B01 - F11 * B00;
            }
            sP4[w][f] = make_float4(P00, P01, P10, P11);
        }
    }
    __syncwarp();

    // --- T stage (scalar compute, packed result) ---------------------------
    const int z0 = lane;
    const int z1 = 32 + (lane & 31 & 15);
    float T0a[6] = {}, T1a[6] = {}, T0b[6] = {}, T1b[6] = {};
#pragma unroll
    for (int nu = 0; nu < 6; nu++) {
        float2 ca = strigT[nu][z0];
        float2 cb = strigT[nu][z1];
#pragma unroll
        for (int mu = 0; mu < 6; mu++) {
            float4 P = sP4[w][mu * 6 + nu];
            T0a[mu] += P.x * ca.x + P.y * ca.y;
            T1a[mu] += P.z * ca.x + P.w * ca.y;
            T0b[mu] += P.x * cb.x + P.y * cb.y;
            T1b[mu] += P.z * cb.x + P.w * cb.y;
        }
    }
    u64 T0p[6], T1p[6];
#pragma unroll
    for (int mu = 0; mu < 6; mu++) {
        T0p[mu] = pack2(T0a[mu], T0b[mu]);
        T1p[mu] = pack2(T1a[mu], T1b[mu]);
    }

    // --- fused synthesis + activation + U accumulation (all f32x2) ---------
    const float inv_s = 1.f / sqrtf(286.f);
    const float two_inv_s = 2.f / sqrtf(286.f);
    const float actq = g_act * qw[y];
    u64 U2[12];
#pragma unroll
    for (int k = 0; k < 12; k++) U2[k] = 0ULL;
#pragma unroll 4
    for (int x = 0; x < NA; x++) {
        const ulonglong2* cp = (const ulonglong2*)strigX2[x];
        ulonglong2 c01 = cp[0], c23 = cp[1], c45 = cp[2];
        ulonglong2 c67 = cp[3], c89 = cp[4], cAB = cp[5];
        u64 g2 = 0ULL;
        g2 = fma2(c01.x, T0p[0], g2); g2 = fma2(c01.y, T1p[0], g2);
        g2 = fma2(c23.x, T0p[1], g2); g2 = fma2(c23.y, T1p[1], g2);
        g2 = fma2(c45.x, T0p[2], g2); g2 = fma2(c45.y, T1p[2], g2);
        g2 = fma2(c67.x, T0p[3], g2); g2 = fma2(c67.y, T1p[3], g2);
        g2 = fma2(c89.x, T0p[4], g2); g2 = fma2(c89.y, T1p[4], g2);
        g2 = fma2(cAB.x, T0p[5], g2); g2 = fma2(cAB.y, T1p[5], g2);
        float ga, gb;
        unpack2(g2, ga, gb);
        float ea = __expf(two_inv_s * ga);
        float eb = __expf(two_inv_s * gb);
        float ha = actq * (1.0f - 2.0f / (ea + 1.0f));
        float hb = actq * (1.0f - 2.0f / (eb + 1.0f));
        u64 h2 = pack2(ha, hb);
        U2[0]  = fma2(c01.x, h2, U2[0]);  U2[1]  = fma2(c01.y, h2, U2[1]);
        U2[2]  = fma2(c23.x, h2, U2[2]);  U2[3]  = fma2(c23.y, h2, U2[3]);
        U2[4]  = fma2(c45.x, h2, U2[4]);  U2[5]  = fma2(c45.y, h2, U2[5]);
        U2[6]  = fma2(c67.x, h2, U2[6]);  U2[7]  = fma2(c67.y, h2, U2[7]);
        U2[8]  = fma2(c89.x, h2, U2[8]);  U2[9]  = fma2(c89.y, h2, U2[9]);
        U2[10] = fma2(cAB.x, h2, U2[10]); U2[11] = fma2(cAB.y, h2, U2[11]);
    }
    {
        float U0[12], U1[12];
#pragma unroll
        for (int k = 0; k < 12; k++) unpack2(U2[k], U0[k], U1[k]);
#pragma unroll
        for (int mu = 0; mu < 6; mu++)
            sU[w][mu][z0] = make_float2(U0[2 * mu], U0[2 * mu + 1]);
        if (lane < 16) {
#pragma unroll
            for (int mu = 0; mu < 6; mu++)
                sU[w][mu][z1] = make_float2(U1[2 * mu], U1[2 * mu + 1]);
        }
    }
    __syncwarp();

    // --- Q forms (f32x2) + coalesced float4 store [b][y][mn*4] --------------
#pragma unroll
    for (int rep = 0; rep < 2; rep++) {
        int f = lane + rep * 32;
        bool v = f < 36;
        int ff = v ? f : 35;
        int mu = ff / 6, nu = ff % 6;
        u64 Qa = 0ULL, Qb = 0ULL;   // (Q00,Q01), (Q10,Q11)
        for (int z = 0; z < NA; z++) {
            float2 u = sU[w][mu][z];
            u64 cs2 = *(const u64*)&strigT[nu][z];
            Qa = fma2(pack2(u.x, u.x), cs2, Qa);
            Qb = fma2(pack2(u.y, u.y), cs2, Qb);
        }
        if (v) {
            float Q00, Q01, Q10, Q11;
            unpack2(Qa, Q00, Q01);
            unpack2(Qb, Q10, Q11);
            *(float4*)(g_Q + ((size_t)(b * NB + y)) * 144 + f * 4) =
                make_float4(Q00, Q01, Q10, Q11);
        }
    }
}

// ---------------------------------------------------------------------------
// Scatter: pure-LDG, no smem. grid (256 b, 2 o-halves) x 576 threads.
// 4 adjacent lanes split the 24-y sum (6 y each), combine with 2 shfl_xor.
// ---------------------------------------------------------------------------
__global__ __launch_bounds__(576, 3) void scatter_kernel(const float* __restrict__ D,
                                                         float* __restrict__ out) {
    const int b = blockIdx.x;
    const int tid = threadIdx.x;
    int o = blockIdx.y * 144 + (tid >> 2);   // output element
    const int h = tid & 3;                   // y-quarter
    const bool valid = o < DIM;
    if (!valid) o = DIM - 1;                 // clamp: keep lanes alive for shfl

    int l = 5;
    if (o < 165) l = 4;
    if (o < 84)  l = 3;
    if (o < 35)  l = 2;
    if (o < 10)  l = 1;
    if (o < 1)   l = 0;
    int off = c_off[l], dl = 2 * l + 1;
    int k = o - off;
    int r = k / dl, q = k - r * dl;
    int rb = 2 * l - r, qb = 2 * l - q;
    int mu = r < l ? l - r : r - l;
    int nu = q < l ? l - q : q - l;
    float sr_ = (r < l) ? 1.f : -1.f;
    float sq_ = (q > l) ? 1.f : -1.f;
    int i_rq = o;
    int i_rqb = off + r * dl + qb;
    int i_rbq = off + rb * dl + q;
    int i_rbqb = off + rb * dl + qb;
    int mn4 = (mu * 6 + nu) * 4;

    float A0 = 0.f, A1 = 0.f, A2 = 0.f, A3 = 0.f;
#pragma unroll
    for (int yv = 0; yv < 6; yv++) {
        int y = h * 6 + yv;
        float4 Q = *(const float4*)(g_Q + ((size_t)(b * NB + y)) * 144 + mn4);
        const float* By = D + (size_t)y * NA * DIM;
        A0 += Q.x * By[i_rq];
        A1 += Q.y * By[i_rqb];
        A2 += Q.z * By[i_rbq];
        A3 += Q.w * By[i_rbqb];
    }
    float acc = A0 + sq_ * A1 + sr_ * (A2 + sq_ * A3);
    acc += __shfl_xor_sync(0xffffffffu, acc, 1);
    acc += __shfl_xor_sync(0xffffffffu, acc, 2);
    if (valid && h == 0)
        out[(size_t)b * DIM + o] = sqrtf(286.f) * acc;
}

extern "C" void kernel_launch(void* const* d_in, const int* in_sizes, int n_in,
                              void* d_out, int out_size) {
    const float* feat = (const float*)d_in[0];  // [256, 286]
    const float* D    = (const float*)d_in[1];  // [48, 24, 48, 286]
    const float* qw   = (const float*)d_in[2];  // [24]
    float* out        = (float*)d_out;          // [256, 286]

    act_kernel<<<48, 256>>>();
    prep_kernel<<<1, 512>>>(D);
    so3_main<<<dim3(NBATCH, 6), 128>>>(feat, D, qw);
    scatter_kernel<<<dim3(NBATCH, 2), 576>>>(D, out);
}

// round 9
// speedup vs baseline: 1.6876x; 1.0911x over previous
#include <cuda_runtime.h>
#include <math.h>

#define NA 48
#define NB 24
#define DIM 286
#define NBATCH 256
#define NMU 6
#define L5OFF 165

typedef unsigned long long u64;

// f32x2 packed helpers (FFMA2 — PTX-only on sm_103a)
__device__ __forceinline__ u64 pack2(float lo, float hi) {
    u64 r; asm("mov.b64 %0, {%1, %2};" : "=l"(r) : "f"(lo), "f"(hi)); return r;
}
__device__ __forceinline__ void unpack2(u64 v, float& lo, float& hi) {
    asm("mov.b64 {%0, %1}, %2;" : "=f"(lo), "=f"(hi) : "l"(v));
}
__device__ __forceinline__ u64 fma2(u64 a, u64 b, u64 c) {
    u64 r; asm("fma.rn.f32x2 %0, %1, %2, %3;" : "=l"(r) : "l"(a), "l"(b), "l"(c)); return r;
}
__device__ __forceinline__ float ex2a(float x) {
    float r; asm("ex2.approx.f32 %0, %1;" : "=f"(r) : "f"(x)); return r;
}
__device__ __forceinline__ float rcpa(float x) {
    float r; asm("rcp.approx.f32 %0, %1;" : "=f"(r) : "f"(x)); return r;
}

// Scratch (static device globals; no allocation)
__device__ float g_c[NA * NMU];                // cos-like per (x, mu)
__device__ float g_s[NA * NMU];                // sin-like per (x, mu)
__device__ float g_act;                        // normalize2mom constant for tanh
__device__ float g_part[48];                   // partials for activation integral
__device__ float g_Q[NBATCH * NB * 144];       // Q forms [b][y][mn*4+c]

__constant__ int c_off[6] = {0, 1, 10, 35, 84, 165};

// ---------------------------------------------------------------------------
// ACT_CST integral: trapz of tanh(x)^2 * N(0,1) over [-12,12], 100001 pts
// ---------------------------------------------------------------------------
__global__ void act_kernel() {
    int tid = blockIdx.x * blockDim.x + threadIdx.x;  // 48*256 = 12288
    float sum = 0.f;
    for (int i = tid; i <= 100000; i += 12288) {
        float x = -12.f + (float)i * 2.4e-4f;
        float t = tanhf(x);
        float p = __expf(-0.5f * x * x);
        sum += t * t * p;
    }
    for (int o = 16; o; o >>= 1) sum += __shfl_down_sync(0xffffffffu, sum, o);
    __shared__ float ws[8];
    int w = threadIdx.x >> 5;
    if ((threadIdx.x & 31) == 0) ws[w] = sum;
    __syncthreads();
    if (threadIdx.x == 0) {
        float b = 0.f;
        for (int i = 0; i < 8; i++) b += ws[i];
        g_part[blockIdx.x] = b;
    }
}

// ---------------------------------------------------------------------------
// Prep: per-sector 2x2 alpha-rotation (c,s) from the l=5 block of D:
// Ra5[x] = D5[x,0,0] * D5[0,0,0]^T / 11  (Rb orthogonal, Ra(0)=I)
// ---------------------------------------------------------------------------
__global__ void prep_kernel(const float* __restrict__ D) {
    int t = threadIdx.x;
    if (t < NA * NMU) {
        int x = t / NMU, mu = t % NMU;
        int p0 = 5 - mu, p1 = 5 + mu;
        const float* X = D + (size_t)x * NB * NA * DIM + L5OFF;
        const float* Z = D + L5OFF;
        float a00 = 0.f, a01 = 0.f, a10 = 0.f, a11 = 0.f;
        for (int k = 0; k < 11; k++) {
            float xp0 = X[p0 * 11 + k], xp1 = X[p1 * 11 + k];
            float zp0 = Z[p0 * 11 + k], zp1 = Z[p1 * 11 + k];
            a00 += xp0 * zp0; a01 += xp0 * zp1;
            a10 += xp1 * zp0; a11 += xp1 * zp1;
        }
        const float inv11 = 1.f / 11.f;
        g_c[t] = 0.5f * (a00 + a11) * inv11;
        g_s[t] = 0.5f * (a01 - a10) * inv11;
    }
    if (t == 0) {
        float tot = 0.f;
        for (int i = 0; i < 48; i++) tot += g_part[i];
        float I = tot * 2.4e-4f * 0.3989422804014327f;
        g_act = 1.0f / sqrtf(I);
    }
}

// ---------------------------------------------------------------------------
// Main (warp-autonomous, f32x2): grid (b, ys) x 128 threads. Warp w handles
// y = ys*4 + w end-to-end: P -> T(packed regs, prescaled for exp2) ->
// fused synth+tanh+U -> Q. tanh via ex2.approx + rcp.approx (no div.rn).
// ---------------------------------------------------------------------------
__global__ __launch_bounds__(128) void so3_main(const float* __restrict__ feat,
                                                const float* __restrict__ D,
                                                const float* __restrict__ qw) {
    const int b = blockIdx.x;
    const int t = threadIdx.x;
    const int w = t >> 5;
    const int lane = t & 31;
    const int y = blockIdx.y * 4 + w;

    __shared__ float sF[DIM];
    __shared__ __align__(16) u64 strigX2[NA][12];    // [x]: (c0,c0)(s0,s0)...(s5,s5)
    __shared__ float2 strigT[NMU][NA + 1];           // [mu][z], padded row
    __shared__ float sB[4][DIM + 2];                 // per-warp B slice
    __shared__ float4 sP4[4][36];                    // per-warp P forms
    __shared__ __align__(16) float2 sU[4][NMU][NA + 1];  // per-warp U

    for (int i = t; i < DIM; i += 128) sF[i] = feat[b * DIM + i];
    for (int i = t; i < NA * NMU; i += 128) {
        int x = i / NMU, mu = i % NMU;
        float c = g_c[i], s = g_s[i];
        strigX2[x][mu * 2 + 0] = pack2(c, c);
        strigX2[x][mu * 2 + 1] = pack2(s, s);
        strigT[mu][x] = make_float2(c, s);
    }
    {
        const float* Dy = D + (size_t)y * NA * DIM;
        for (int i = lane; i < DIM; i += 32) sB[w][i] = Dy[i];
    }
    __syncthreads();

    // --- P forms (36 over 32 lanes; lanes 0-3 take a second form) ----------
#pragma unroll
    for (int rep = 0; rep < 2; rep++) {
        int f = lane + rep * 32;
        if (f < 36) {
            int mu = f / 6, nu = f % 6;
            float P00 = 0.f, P01 = 0.f, P10 = 0.f, P11 = 0.f;
            int l0 = mu > nu ? mu : nu;
            for (int l = l0; l <= 5; l++) {
                int dl = 2 * l + 1, off = c_off[l];
                int r0 = l - mu, r1 = l + mu, q0 = l - nu, q1 = l + nu;
                float F00 = sF[off + r0 * dl + q0], F01 = sF[off + r0 * dl + q1];
                float F10 = sF[off + r1 * dl + q0], F11 = sF[off + r1 * dl + q1];
                float B00 = sB[w][off + r0 * dl + q0], B01 = sB[w][off + r0 * dl + q1];
                float B10 = sB[w][off + r1 * dl + q0], B11 = sB[w][off + r1 * dl + q1];
                if (mu == 0) { F10 = F11 = 0.f; B10 = B11 = 0.f; }
                if (nu == 0) { F01 = F11 = 0.f; B01 = B11 = 0.f; }
                P00 +=  F00 * B00 + F01 * B01 + F10 * B10 + F11 * B11;
                P01 += -F00 * B01 + F01 * B00 - F10 * B11 + F11 * B10;
                P10 +=  F00 * B10 + F01 * B11 - F10 * B00 - F11 * B01;
                P11 += -F00 * B11 + F01 * B10 + F10 * B01 - F11 * B00;
            }
            sP4[w][f] = make_float4(P00, P01, P10, P11);
        }
    }
    __syncwarp();

    // --- T stage (scalar compute, packed result; prescaled for exp2) -------
    const int z0 = lane;
    const int z1 = 32 + (lane & 15);
    float T0a[6] = {}, T1a[6] = {}, T0b[6] = {}, T1b[6] = {};
#pragma unroll
    for (int nu = 0; nu < 6; nu++) {
        float2 ca = strigT[nu][z0];
        float2 cb = strigT[nu][z1];
#pragma unroll
        for (int mu = 0; mu < 6; mu++) {
            float4 P = sP4[w][mu * 6 + nu];
            T0a[mu] += P.x * ca.x + P.y * ca.y;
            T1a[mu] += P.z * ca.x + P.w * ca.y;
            T0b[mu] += P.x * cb.x + P.y * cb.y;
            T1b[mu] += P.z * cb.x + P.w * cb.y;
        }
    }
    // K = 2*inv_s*log2(e): g_scaled = K*g so e^{2 g inv_s} = 2^{g_scaled}
    const float K = 2.f / sqrtf(286.f) * 1.4426950408889634f;
    u64 T0p[6], T1p[6];
#pragma unroll
    for (int mu = 0; mu < 6; mu++) {
        T0p[mu] = pack2(T0a[mu] * K, T0b[mu] * K);
        T1p[mu] = pack2(T1a[mu] * K, T1b[mu] * K);
    }

    // --- fused synthesis + activation + U accumulation (all f32x2) ---------
    const float actq = g_act * qw[y];
    const float m2actq = -2.0f * actq;
    u64 U2[12];
#pragma unroll
    for (int k = 0; k < 12; k++) U2[k] = 0ULL;
#pragma unroll 4
    for (int x = 0; x < NA; x++) {
        const ulonglong2* cp = (const ulonglong2*)strigX2[x];
        ulonglong2 c01 = cp[0], c23 = cp[1], c45 = cp[2];
        ulonglong2 c67 = cp[3], c89 = cp[4], cAB = cp[5];
        u64 g2 = 0ULL;
        g2 = fma2(c01.x, T0p[0], g2); g2 = fma2(c01.y, T1p[0], g2);
        g2 = fma2(c23.x, T0p[1], g2); g2 = fma2(c23.y, T1p[1], g2);
        g2 = fma2(c45.x, T0p[2], g2); g2 = fma2(c45.y, T1p[2], g2);
        g2 = fma2(c67.x, T0p[3], g2); g2 = fma2(c67.y, T1p[3], g2);
        g2 = fma2(c89.x, T0p[4], g2); g2 = fma2(c89.y, T1p[4], g2);
        g2 = fma2(cAB.x, T0p[5], g2); g2 = fma2(cAB.y, T1p[5], g2);
        float ga, gb;
        unpack2(g2, ga, gb);
        // tanh(v) = 1 - 2/(2^{Kg}+1), h = actq*tanh = fma(-2actq, rcp, actq)
        float ha = fmaf(m2actq, rcpa(ex2a(ga) + 1.0f), actq);
        float hb = fmaf(m2actq, rcpa(ex2a(gb) + 1.0f), actq);
        u64 h2 = pack2(ha, hb);
        U2[0]  = fma2(c01.x, h2, U2[0]);  U2[1]  = fma2(c01.y, h2, U2[1]);
        U2[2]  = fma2(c23.x, h2, U2[2]);  U2[3]  = fma2(c23.y, h2, U2[3]);
        U2[4]  = fma2(c45.x, h2, U2[4]);  U2[5]  = fma2(c45.y, h2, U2[5]);
        U2[6]  = fma2(c67.x, h2, U2[6]);  U2[7]  = fma2(c67.y, h2, U2[7]);
        U2[8]  = fma2(c89.x, h2, U2[8]);  U2[9]  = fma2(c89.y, h2, U2[9]);
        U2[10] = fma2(cAB.x, h2, U2[10]); U2[11] = fma2(cAB.y, h2, U2[11]);
    }
    {
        float U0[12], U1[12];
#pragma unroll
        for (int k = 0; k < 12; k++) unpack2(U2[k], U0[k], U1[k]);
#pragma unroll
        for (int mu = 0; mu < 6; mu++)
            sU[w][mu][z0] = make_float2(U0[2 * mu], U0[2 * mu + 1]);
        if (lane < 16) {
#pragma unroll
            for (int mu = 0; mu < 6; mu++)
                sU[w][mu][z1] = make_float2(U1[2 * mu], U1[2 * mu + 1]);
        }
    }
    __syncwarp();

    // --- Q forms (f32x2, splat table = strigX2 rows) ------------------------
#pragma unroll
    for (int rep = 0; rep < 2; rep++) {
        int f = lane + rep * 32;
        bool v = f < 36;
        int ff = v ? f : 35;
        int mu = ff / 6, nu = ff % 6;
        u64 Qa = 0ULL, Qb = 0ULL;   // (Q00,Q10), (Q01,Q11)
        for (int z = 0; z < NA; z++) {
            u64 u2 = *(const u64*)&sU[w][mu][z];            // (Uc, Us)
            ulonglong2 cs = *(const ulonglong2*)&strigX2[z][2 * nu];  // (c,c),(s,s)
            Qa = fma2(u2, cs.x, Qa);
            Qb = fma2(u2, cs.y, Qb);
        }
        if (v) {
            float Q00, Q10, Q01, Q11;
            unpack2(Qa, Q00, Q10);
            unpack2(Qb, Q01, Q11);
            *(float4*)(g_Q + ((size_t)(b * NB + y)) * 144 + f * 4) =
                make_float4(Q00, Q01, Q10, Q11);
        }
    }
}

// ---------------------------------------------------------------------------
// Scatter: grid (256 b, 2 o-halves) x 576 threads. Q[b] (13.8KB) staged in
// smem (coalesced LDG, padded rows for bank spread); B stays LDG (L1-hot).
// 4 adjacent lanes split the 24-y sum (6 y each), combine with 2 shfl_xor.
// ---------------------------------------------------------------------------
#define QPAD 156
__global__ __launch_bounds__(576, 3) void scatter_kernel(const float* __restrict__ D,
                                                         float* __restrict__ out) {
    const int b = blockIdx.x;
    const int tid = threadIdx.x;
    __shared__ __align__(16) float sQ[NB * QPAD];

    const float* Qb = g_Q + (size_t)b * NB * 144;
    for (int i = tid; i < NB * 144; i += 576) {
        int yy = i / 144, kk = i - yy * 144;
        sQ[yy * QPAD + kk] = Qb[i];
    }
    __syncthreads();

    int o = blockIdx.y * 144 + (tid >> 2);   // output element
    const int h = tid & 3;                   // y-quarter
    const bool valid = o < DIM;
    if (!valid) o = DIM - 1;                 // clamp: keep lanes alive for shfl

    int l = 5;
    if (o < 165) l = 4;
    if (o < 84)  l = 3;
    if (o < 35)  l = 2;
    if (o < 10)  l = 1;
    if (o < 1)   l = 0;
    int off = c_off[l], dl = 2 * l + 1;
    int k = o - off;
    int r = k / dl, q = k - r * dl;
    int rb = 2 * l - r, qb = 2 * l - q;
    int mu = r < l ? l - r : r - l;
    int nu = q < l ? l - q : q - l;
    float sr_ = (r < l) ? 1.f : -1.f;
    float sq_ = (q > l) ? 1.f : -1.f;
    int i_rq = o;
    int i_rqb = off + r * dl + qb;
    int i_rbq = off + rb * dl + q;
    int i_rbqb = off + rb * dl + qb;
    int mn4 = (mu * 6 + nu) * 4;

    float A0 = 0.f, A1 = 0.f, A2 = 0.f, A3 = 0.f;
#pragma unroll
    for (int yv = 0; yv < 6; yv++) {
        int y = h * 6 + yv;
        float4 Q = *(const float4*)(sQ + y * QPAD + mn4);
        const float* By = D + (size_t)y * NA * DIM;
        A0 += Q.x * By[i_rq];
        A1 += Q.y * By[i_rqb];
        A2 += Q.z * By[i_rbq];
        A3 += Q.w * By[i_rbqb];
    }
    float acc = A0 + sq_ * A1 + sr_ * (A2 + sq_ * A3);
    acc += __shfl_xor_sync(0xffffffffu, acc, 1);
    acc += __shfl_xor_sync(0xffffffffu, acc, 2);
    if (valid && h == 0)
        out[(size_t)b * DIM + o] = sqrtf(286.f) * acc;
}

extern "C" void kernel_launch(void* const* d_in, const int* in_sizes, int n_in,
                              void* d_out, int out_size) {
    const float* feat = (const float*)d_in[0];  // [256, 286]
    const float* D    = (const float*)d_in[1];  // [48, 24, 48, 286]
    const float* qw   = (const float*)d_in[2];  // [24]
    float* out        = (float*)d_out;          // [256, 286]

    act_kernel<<<48, 256>>>();
    prep_kernel<<<1, 512>>>(D);
    so3_main<<<dim3(NBATCH, 6), 128>>>(feat, D, qw);
    scatter_kernel<<<dim3(NBATCH, 2), 576>>>(D, out);
}

// round 10
// speedup vs baseline: 1.6946x; 1.0041x over previous
#include <cuda_runtime.h>
#include <math.h>

#define NA 48
#define NB 24
#define DIM 286
#define NBATCH 256
#define NMU 6
#define L5OFF 165

typedef unsigned long long u64;

// f32x2 packed helpers (FFMA2 — PTX-only on sm_103a)
__device__ __forceinline__ u64 pack2(float lo, float hi) {
    u64 r; asm("mov.b64 %0, {%1, %2};" : "=l"(r) : "f"(lo), "f"(hi)); return r;
}
__device__ __forceinline__ void unpack2(u64 v, float& lo, float& hi) {
    asm("mov.b64 {%0, %1}, %2;" : "=f"(lo), "=f"(hi) : "l"(v));
}
__device__ __forceinline__ u64 fma2(u64 a, u64 b, u64 c) {
    u64 r; asm("fma.rn.f32x2 %0, %1, %2, %3;" : "=l"(r) : "l"(a), "l"(b), "l"(c)); return r;
}
__device__ __forceinline__ u64 add2(u64 a, u64 b) {
    u64 r; asm("add.rn.f32x2 %0, %1, %2;" : "=l"(r) : "l"(a), "l"(b)); return r;
}
__device__ __forceinline__ float ex2a(float x) {
    float r; asm("ex2.approx.f32 %0, %1;" : "=f"(r) : "f"(x)); return r;
}
__device__ __forceinline__ float rcpa(float x) {
    float r; asm("rcp.approx.f32 %0, %1;" : "=f"(r) : "f"(x)); return r;
}

// Scratch (static device globals; no allocation)
__device__ float g_c[NA * NMU];                // cos-like per (x, mu)
__device__ float g_s[NA * NMU];                // sin-like per (x, mu)
__device__ float g_act;                        // normalize2mom constant for tanh
__device__ float g_part[48];                   // partials for activation integral
__device__ float g_Q[NBATCH * NB * 144];       // Q forms [b][y][mn*4+c]

__constant__ int c_off[6] = {0, 1, 10, 35, 84, 165};

// ---------------------------------------------------------------------------
// ACT_CST integral: trapz of tanh(x)^2 * N(0,1) over [-12,12], 100001 pts
// tanh via ex2/rcp chain (err ~1e-6 rel on the integral — invisible)
// ---------------------------------------------------------------------------
__global__ void act_kernel() {
    const float L2E2 = 2.8853900817779268f;  // 2*log2(e)
    int tid = blockIdx.x * blockDim.x + threadIdx.x;  // 48*256 = 12288
    float sum = 0.f;
    for (int i = tid; i <= 100000; i += 12288) {
        float x = -12.f + (float)i * 2.4e-4f;
        float t = 1.0f - 2.0f * rcpa(ex2a(x * L2E2) + 1.0f);
        float p = __expf(-0.5f * x * x);
        sum += t * t * p;
    }
    for (int o = 16; o; o >>= 1) sum += __shfl_down_sync(0xffffffffu, sum, o);
    __shared__ float ws[8];
    int w = threadIdx.x >> 5;
    if ((threadIdx.x & 31) == 0) ws[w] = sum;
    __syncthreads();
    if (threadIdx.x == 0) {
        float b = 0.f;
        for (int i = 0; i < 8; i++) b += ws[i];
        g_part[blockIdx.x] = b;
    }
}

// ---------------------------------------------------------------------------
// Prep: per-sector 2x2 alpha-rotation (c,s) from the l=5 block of D:
// Ra5[x] = D5[x,0,0] * D5[0,0,0]^T / 11  (Rb orthogonal, Ra(0)=I)
// ---------------------------------------------------------------------------
__global__ void prep_kernel(const float* __restrict__ D) {
    int t = threadIdx.x;
    if (t < NA * NMU) {
        int x = t / NMU, mu = t % NMU;
        int p0 = 5 - mu, p1 = 5 + mu;
        const float* X = D + (size_t)x * NB * NA * DIM + L5OFF;
        const float* Z = D + L5OFF;
        float a00 = 0.f, a01 = 0.f, a10 = 0.f, a11 = 0.f;
        for (int k = 0; k < 11; k++) {
            float xp0 = X[p0 * 11 + k], xp1 = X[p1 * 11 + k];
            float zp0 = Z[p0 * 11 + k], zp1 = Z[p1 * 11 + k];
            a00 += xp0 * zp0; a01 += xp0 * zp1;
            a10 += xp1 * zp0; a11 += xp1 * zp1;
        }
        const float inv11 = 1.f / 11.f;
        g_c[t] = 0.5f * (a00 + a11) * inv11;
        g_s[t] = 0.5f * (a01 - a10) * inv11;
    }
    if (t == 0) {
        float tot = 0.f;
        for (int i = 0; i < 48; i++) tot += g_part[i];
        float I = tot * 2.4e-4f * 0.3989422804014327f;
        g_act = 1.0f / sqrtf(I);
    }
}

// ---------------------------------------------------------------------------
// Main (warp-autonomous, f32x2): grid (b, ys) x 128 threads. Warp w handles
// y = ys*4 + w end-to-end: P -> T(packed regs, prescaled for exp2) ->
// fused synth+tanh+U -> Q. tanh via ex2.approx + rcp.approx.
// ---------------------------------------------------------------------------
__global__ __launch_bounds__(128) void so3_main(const float* __restrict__ feat,
                                                const float* __restrict__ D,
                                                const float* __restrict__ qw) {
    const int b = blockIdx.x;
    const int t = threadIdx.x;
    const int w = t >> 5;
    const int lane = t & 31;
    const int y = blockIdx.y * 4 + w;

    __shared__ float sF[DIM];
    __shared__ __align__(16) u64 strigX2[NA][12];    // [x]: (c0,c0)(s0,s0)...(s5,s5)
    __shared__ float2 strigT[NMU][NA + 1];           // [mu][z], padded row
    __shared__ float sB[4][DIM + 2];                 // per-warp B slice
    __shared__ float4 sP4[4][36];                    // per-warp P forms
    __shared__ __align__(16) float2 sU[4][NMU][NA + 1];  // per-warp U

    for (int i = t; i < DIM; i += 128) sF[i] = feat[b * DIM + i];
    for (int i = t; i < NA * NMU; i += 128) {
        int x = i / NMU, mu = i % NMU;
        float c = g_c[i], s = g_s[i];
        strigX2[x][mu * 2 + 0] = pack2(c, c);
        strigX2[x][mu * 2 + 1] = pack2(s, s);
        strigT[mu][x] = make_float2(c, s);
    }
    {
        const float* Dy = D + (size_t)y * NA * DIM;
        for (int i = lane; i < DIM; i += 32) sB[w][i] = Dy[i];
    }
    __syncthreads();

    // --- P forms (36 over 32 lanes; lanes 0-3 take a second form) ----------
#pragma unroll
    for (int rep = 0; rep < 2; rep++) {
        int f = lane + rep * 32;
        if (f < 36) {
            int mu = f / 6, nu = f % 6;
            float P00 = 0.f, P01 = 0.f, P10 = 0.f, P11 = 0.f;
            int l0 = mu > nu ? mu : nu;
            for (int l = l0; l <= 5; l++) {
                int dl = 2 * l + 1, off = c_off[l];
                int r0 = l - mu, r1 = l + mu, q0 = l - nu, q1 = l + nu;
                float F00 = sF[off + r0 * dl + q0], F01 = sF[off + r0 * dl + q1];
                float F10 = sF[off + r1 * dl + q0], F11 = sF[off + r1 * dl + q1];
                float B00 = sB[w][off + r0 * dl + q0], B01 = sB[w][off + r0 * dl + q1];
                float B10 = sB[w][off + r1 * dl + q0], B11 = sB[w][off + r1 * dl + q1];
                if (mu == 0) { F10 = F11 = 0.f; B10 = B11 = 0.f; }
                if (nu == 0) { F01 = F11 = 0.f; B01 = B11 = 0.f; }
                P00 +=  F00 * B00 + F01 * B01 + F10 * B10 + F11 * B11;
                P01 += -F00 * B01 + F01 * B00 - F10 * B11 + F11 * B10;
                P10 +=  F00 * B10 + F01 * B11 - F10 * B00 - F11 * B01;
                P11 += -F00 * B11 + F01 * B10 + F10 * B01 - F11 * B00;
            }
            sP4[w][f] = make_float4(P00, P01, P10, P11);
        }
    }
    __syncwarp();

    // --- T stage (scalar compute, packed result; prescaled for exp2) -------
    const int z0 = lane;
    const int z1 = 32 + (lane & 15);
    float T0a[6] = {}, T1a[6] = {}, T0b[6] = {}, T1b[6] = {};
#pragma unroll
    for (int nu = 0; nu < 6; nu++) {
        float2 ca = strigT[nu][z0];
        float2 cb = strigT[nu][z1];
#pragma unroll
        for (int mu = 0; mu < 6; mu++) {
            float4 P = sP4[w][mu * 6 + nu];
            T0a[mu] += P.x * ca.x + P.y * ca.y;
            T1a[mu] += P.z * ca.x + P.w * ca.y;
            T0b[mu] += P.x * cb.x + P.y * cb.y;
            T1b[mu] += P.z * cb.x + P.w * cb.y;
        }
    }
    // K = 2*inv_s*log2(e): g_scaled = K*g so e^{2 g inv_s} = 2^{g_scaled}
    const float K = 2.f / sqrtf(286.f) * 1.4426950408889634f;
    u64 T0p[6], T1p[6];
#pragma unroll
    for (int mu = 0; mu < 6; mu++) {
        T0p[mu] = pack2(T0a[mu] * K, T0b[mu] * K);
        T1p[mu] = pack2(T1a[mu] * K, T1b[mu] * K);
    }

    // --- fused synthesis + activation + U accumulation (all f32x2) ---------
    const float actq = g_act * qw[y];
    const float m2actq = -2.0f * actq;
    u64 U2[12];
#pragma unroll
    for (int k = 0; k < 12; k++) U2[k] = 0ULL;
#pragma unroll 4
    for (int x = 0; x < NA; x++) {
        const ulonglong2* cp = (const ulonglong2*)strigX2[x];
        ulonglong2 c01 = cp[0], c23 = cp[1], c45 = cp[2];
        ulonglong2 c67 = cp[3], c89 = cp[4], cAB = cp[5];
        u64 g2 = 0ULL;
        g2 = fma2(c01.x, T0p[0], g2); g2 = fma2(c01.y, T1p[0], g2);
        g2 = fma2(c23.x, T0p[1], g2); g2 = fma2(c23.y, T1p[1], g2);
        g2 = fma2(c45.x, T0p[2], g2); g2 = fma2(c45.y, T1p[2], g2);
        g2 = fma2(c67.x, T0p[3], g2); g2 = fma2(c67.y, T1p[3], g2);
        g2 = fma2(c89.x, T0p[4], g2); g2 = fma2(c89.y, T1p[4], g2);
        g2 = fma2(cAB.x, T0p[5], g2); g2 = fma2(cAB.y, T1p[5], g2);
        float ga, gb;
        unpack2(g2, ga, gb);
        float ha = fmaf(m2actq, rcpa(ex2a(ga) + 1.0f), actq);
        float hb = fmaf(m2actq, rcpa(ex2a(gb) + 1.0f), actq);
        u64 h2 = pack2(ha, hb);
        U2[0]  = fma2(c01.x, h2, U2[0]);  U2[1]  = fma2(c01.y, h2, U2[1]);
        U2[2]  = fma2(c23.x, h2, U2[2]);  U2[3]  = fma2(c23.y, h2, U2[3]);
        U2[4]  = fma2(c45.x, h2, U2[4]);  U2[5]  = fma2(c45.y, h2, U2[5]);
        U2[6]  = fma2(c67.x, h2, U2[6]);  U2[7]  = fma2(c67.y, h2, U2[7]);
        U2[8]  = fma2(c89.x, h2, U2[8]);  U2[9]  = fma2(c89.y, h2, U2[9]);
        U2[10] = fma2(cAB.x, h2, U2[10]); U2[11] = fma2(cAB.y, h2, U2[11]);
    }
    {
        float U0[12], U1[12];
#pragma unroll
        for (int k = 0; k < 12; k++) unpack2(U2[k], U0[k], U1[k]);
#pragma unroll
        for (int mu = 0; mu < 6; mu++)
            sU[w][mu][z0] = make_float2(U0[2 * mu], U0[2 * mu + 1]);
        if (lane < 16) {
#pragma unroll
            for (int mu = 0; mu < 6; mu++)
                sU[w][mu][z1] = make_float2(U1[2 * mu], U1[2 * mu + 1]);
        }
    }
    __syncwarp();

    // --- Q forms part 1: forms 0..31, one per lane, full z-loop ------------
    {
        int mu = lane / 6, nu = lane % 6;
        u64 Qa = 0ULL, Qb = 0ULL;   // (Q00,Q10), (Q01,Q11)
        for (int z = 0; z < NA; z++) {
            u64 u2 = *(const u64*)&sU[w][mu][z];                      // (Uc, Us)
            ulonglong2 cs = *(const ulonglong2*)&strigX2[z][2 * nu];  // (c,c),(s,s)
            Qa = fma2(u2, cs.x, Qa);
            Qb = fma2(u2, cs.y, Qb);
        }
        float Q00, Q10, Q01, Q11;
        unpack2(Qa, Q00, Q10);
        unpack2(Qb, Q01, Q11);
        *(float4*)(g_Q + ((size_t)(b * NB + y)) * 144 + lane * 4) =
            make_float4(Q00, Q01, Q10, Q11);
    }
    // --- Q forms part 2: forms 32..35 (mu=5, nu=2..5) over 8-lane groups ---
    {
        int grp = lane >> 3;            // 0..3 -> form 32+grp
        int nu = 2 + grp;
        u64 Qa = 0ULL, Qb = 0ULL;
#pragma unroll
        for (int k = 0; k < 6; k++) {
            int z = (lane & 7) * 6 + k;
            u64 u2 = *(const u64*)&sU[w][5][z];
            ulonglong2 cs = *(const ulonglong2*)&strigX2[z][2 * nu];
            Qa = fma2(u2, cs.x, Qa);
            Qb = fma2(u2, cs.y, Qb);
        }
#pragma unroll
        for (int off = 1; off < 8; off <<= 1) {
            Qa = add2(Qa, __shfl_xor_sync(0xffffffffu, Qa, off));
            Qb = add2(Qb, __shfl_xor_sync(0xffffffffu, Qb, off));
        }
        if ((lane & 7) == 0) {
            float Q00, Q10, Q01, Q11;
            unpack2(Qa, Q00, Q10);
            unpack2(Qb, Q01, Q11);
            *(float4*)(g_Q + ((size_t)(b * NB + y)) * 144 + (32 + grp) * 4) =
                make_float4(Q00, Q01, Q10, Q11);
        }
    }
}

// ---------------------------------------------------------------------------
// Scatter: pure-LDG, wave-friendly. grid (256 b, 5 o-chunks) x 256 threads
// (64 o x 4 h-lanes). 8 blocks/SM -> 1.08 waves. Q is L2-hot (5 CTAs per b).
// ---------------------------------------------------------------------------
__global__ __launch_bounds__(256) void scatter_kernel(const float* __restrict__ D,
                                                      float* __restrict__ out) {
    const int b = blockIdx.x;
    const int tid = threadIdx.x;
    int o = blockIdx.y * 64 + (tid >> 2);    // output element
    const int h = tid & 3;                   // y-quarter
    const bool valid = o < DIM;
    if (!valid) o = DIM - 1;                 // clamp: keep lanes alive for shfl

    int l = 5;
    if (o < 165) l = 4;
    if (o < 84)  l = 3;
    if (o < 35)  l = 2;
    if (o < 10)  l = 1;
    if (o < 1)   l = 0;
    int off = c_off[l], dl = 2 * l + 1;
    int k = o - off;
    int r = k / dl, q = k - r * dl;
    int rb = 2 * l - r, qb = 2 * l - q;
    int mu = r < l ? l - r : r - l;
    int nu = q < l ? l - q : q - l;
    float sr_ = (r < l) ? 1.f : -1.f;
    float sq_ = (q > l) ? 1.f : -1.f;
    int i_rq = o;
    int i_rqb = off + r * dl + qb;
    int i_rbq = off + rb * dl + q;
    int i_rbqb = off + rb * dl + qb;
    int mn4 = (mu * 6 + nu) * 4;

    float A0 = 0.f, A1 = 0.f, A2 = 0.f, A3 = 0.f;
#pragma unroll
    for (int yv = 0; yv < 6; yv++) {
        int y = h * 6 + yv;
        float4 Q = *(const float4*)(g_Q + ((size_t)(b * NB + y)) * 144 + mn4);
        const float* By = D + (size_t)y * NA * DIM;
        A0 += Q.x * By[i_rq];
        A1 += Q.y * By[i_rqb];
        A2 += Q.z * By[i_rbq];
        A3 += Q.w * By[i_rbqb];
    }
    float acc = A0 + sq_ * A1 + sr_ * (A2 + sq_ * A3);
    acc += __shfl_xor_sync(0xffffffffu, acc, 1);
    acc += __shfl_xor_sync(0xffffffffu, acc, 2);
    if (valid && h == 0)
        out[(size_t)b * DIM + o] = sqrtf(286.f) * acc;
}

extern "C" void kernel_launch(void* const* d_in, const int* in_sizes, int n_in,
                              void* d_out, int out_size) {
    const float* feat = (const float*)d_in[0];  // [256, 286]
    const float* D    = (const float*)d_in[1];  // [48, 24, 48, 286]
    const float* qw   = (const float*)d_in[2];  // [24]
    float* out        = (float*)d_out;          // [256, 286]

    act_kernel<<<48, 256>>>();
    prep_kernel<<<1, 512>>>(D);
    so3_main<<<dim3(NBATCH, 6), 128>>>(feat, D, qw);
    scatter_kernel<<<dim3(NBATCH, 5), 256>>>(D, out);
}

// round 12
// speedup vs baseline: 1.8802x; 1.1095x over previous
#include <cuda_runtime.h>
#include <math.h>

#define NA 48
#define NB 24
#define DIM 286
#define NBATCH 256
#define NMU 6
#define L5OFF 165

typedef unsigned long long u64;

// f32x2 packed helpers (FFMA2 — PTX-only on sm_103a)
__device__ __forceinline__ u64 pack2(float lo, float hi) {
    u64 r; asm("mov.b64 %0, {%1, %2};" : "=l"(r) : "f"(lo), "f"(hi)); return r;
}
__device__ __forceinline__ void unpack2(u64 v, float& lo, float& hi) {
    asm("mov.b64 {%0, %1}, %2;" : "=f"(lo), "=f"(hi) : "l"(v));
}
__device__ __forceinline__ u64 fma2(u64 a, u64 b, u64 c) {
    u64 r; asm("fma.rn.f32x2 %0, %1, %2, %3;" : "=l"(r) : "l"(a), "l"(b), "l"(c)); return r;
}
__device__ __forceinline__ u64 add2(u64 a, u64 b) {
    u64 r; asm("add.rn.f32x2 %0, %1, %2;" : "=l"(r) : "l"(a), "l"(b)); return r;
}
__device__ __forceinline__ float ex2a(float x) {
    float r; asm("ex2.approx.f32 %0, %1;" : "=f"(r) : "f"(x)); return r;
}
__device__ __forceinline__ float rcpa(float x) {
    float r; asm("rcp.approx.f32 %0, %1;" : "=f"(r) : "f"(x)); return r;
}

// Scratch (static device globals; no allocation)
__device__ float g_c[NA * NMU];                // cos-like per (x, mu)
__device__ float g_s[NA * NMU];                // sin-like per (x, mu)
__device__ float g_act;                        // normalize2mom constant for tanh
__device__ float g_part[48];                   // partials for activation integral
__device__ float g_Q[NBATCH * NB * 144];       // Q forms [b][y][mn*4+c]

__constant__ int c_off[6] = {0, 1, 10, 35, 84, 165};

// ---------------------------------------------------------------------------
// ACT_CST integral: trapz of tanh(x)^2 * N(0,1) over [-12,12], 100001 pts
// ---------------------------------------------------------------------------
__global__ void act_kernel() {
    const float L2E2 = 2.8853900817779268f;  // 2*log2(e)
    int tid = blockIdx.x * blockDim.x + threadIdx.x;  // 48*256 = 12288
    float sum = 0.f;
    for (int i = tid; i <= 100000; i += 12288) {
        float x = -12.f + (float)i * 2.4e-4f;
        float t = 1.0f - 2.0f * rcpa(ex2a(x * L2E2) + 1.0f);
        float p = __expf(-0.5f * x * x);
        sum += t * t * p;
    }
    for (int o = 16; o; o >>= 1) sum += __shfl_down_sync(0xffffffffu, sum, o);
    __shared__ float ws[8];
    int w = threadIdx.x >> 5;
    if ((threadIdx.x & 31) == 0) ws[w] = sum;
    __syncthreads();
    if (threadIdx.x == 0) {
        float b = 0.f;
        for (int i = 0; i < 8; i++) b += ws[i];
        g_part[blockIdx.x] = b;
    }
}

// ---------------------------------------------------------------------------
// Prep: per-sector 2x2 alpha-rotation (c,s) from the l=5 block of D
// ---------------------------------------------------------------------------
__global__ void prep_kernel(const float* __restrict__ D) {
    int t = threadIdx.x;
    if (t < NA * NMU) {
        int x = t / NMU, mu = t % NMU;
        int p0 = 5 - mu, p1 = 5 + mu;
        const float* X = D + (size_t)x * NB * NA * DIM + L5OFF;
        const float* Z = D + L5OFF;
        float a00 = 0.f, a01 = 0.f, a10 = 0.f, a11 = 0.f;
        for (int k = 0; k < 11; k++) {
            float xp0 = X[p0 * 11 + k], xp1 = X[p1 * 11 + k];
            float zp0 = Z[p0 * 11 + k], zp1 = Z[p1 * 11 + k];
            a00 += xp0 * zp0; a01 += xp0 * zp1;
            a10 += xp1 * zp0; a11 += xp1 * zp1;
        }
        const float inv11 = 1.f / 11.f;
        g_c[t] = 0.5f * (a00 + a11) * inv11;
        g_s[t] = 0.5f * (a01 - a10) * inv11;
    }
    if (t == 0) {
        float tot = 0.f;
        for (int i = 0; i < 48; i++) tot += g_part[i];
        float I = tot * 2.4e-4f * 0.3989422804014327f;
        g_act = 1.0f / sqrtf(I);
    }
}

// ---------------------------------------------------------------------------
// Main (warp-autonomous, f32x2): grid (b, ys) x 128 threads. Warp w handles
// y = ys*4 + w. P (K-prescaled, B via L1-hot LDG) -> T(packed) ->
// fused synth+tanh+U -> Q.
// ---------------------------------------------------------------------------
__global__ __launch_bounds__(128) void so3_main(const float* __restrict__ feat,
                                                const float* __restrict__ D,
                                                const float* __restrict__ qw) {
    const int b = blockIdx.x;
    const int t = threadIdx.x;
    const int w = t >> 5;
    const int lane = t & 31;
    const int y = blockIdx.y * 4 + w;

    __shared__ float sF[DIM];
    __shared__ __align__(16) u64 strigX2[NA][12];    // [x]: (c0,c0)(s0,s0)...(s5,s5)
    __shared__ float2 strigT[NMU][NA + 1];           // [mu][z], padded row
    __shared__ float4 sP4[4][36];                    // per-warp P forms (K-prescaled)
    __shared__ __align__(16) float2 sU[4][NMU][NA + 1];  // per-warp U

    for (int i = t; i < DIM; i += 128) sF[i] = feat[b * DIM + i];
    for (int i = t; i < NA * NMU; i += 128) {
        int x = i / NMU, mu = i % NMU;
        float c = g_c[i], s = g_s[i];
        strigX2[x][mu * 2 + 0] = pack2(c, c);
        strigX2[x][mu * 2 + 1] = pack2(s, s);
        strigT[mu][x] = make_float2(c, s);
    }
    __syncthreads();

    // K = 2*inv_s*log2(e): fold into P so synthesis output is exp2-ready
    const float K = 2.f / sqrtf(286.f) * 1.4426950408889634f;
    const float* By_g = D + (size_t)y * NA * DIM;   // D[0][y][0][:], L1/L2-hot

    // --- P forms (36 over 32 lanes; lanes 0-3 take a second form) ----------
#pragma unroll
    for (int rep = 0; rep < 2; rep++) {
        int f = lane + rep * 32;
        if (f < 36) {
            int mu = f / 6, nu = f % 6;
            float P00 = 0.f, P01 = 0.f, P10 = 0.f, P11 = 0.f;
            int l0 = mu > nu ? mu : nu;
            for (int l = l0; l <= 5; l++) {
                int dl = 2 * l + 1, off = c_off[l];
                int r0 = l - mu, r1 = l + mu, q0 = l - nu, q1 = l + nu;
                float F00 = sF[off + r0 * dl + q0], F01 = sF[off + r0 * dl + q1];
                float F10 = sF[off + r1 * dl + q0], F11 = sF[off + r1 * dl + q1];
                float B00 = By_g[off + r0 * dl + q0], B01 = By_g[off + r0 * dl + q1];
                float B10 = By_g[off + r1 * dl + q0], B11 = By_g[off + r1 * dl + q1];
                if (mu == 0) { F10 = F11 = 0.f; B10 = B11 = 0.f; }
                if (nu == 0) { F01 = F11 = 0.f; B01 = B11 = 0.f; }
                P00 +=  F00 * B00 + F01 * B01 + F10 * B10 + F11 * B11;
                P01 += -F00 * B01 + F01 * B00 - F10 * B11 + F11 * B10;
                P10 +=  F00 * B10 + F01 * B11 - F10 * B00 - F11 * B01;
                P11 += -F00 * B11 + F01 * B10 + F10 * B01 - F11 * B00;
            }
            sP4[w][f] = make_float4(P00 * K, P01 * K, P10 * K, P11 * K);
        }
    }
    __syncwarp();

    // --- T stage (packed f32x2: (z0,z1) lanes) ------------------------------
    const int z0 = lane;
    const int z1 = 32 + (lane & 15);
    u64 T0p[6], T1p[6];
#pragma unroll
    for (int mu = 0; mu < 6; mu++) { T0p[mu] = 0ULL; T1p[mu] = 0ULL; }
#pragma unroll
    for (int nu = 0; nu < 6; nu++) {
        float2 ca = strigT[nu][z0];
        float2 cb = strigT[nu][z1];
        u64 cpk = pack2(ca.x, cb.x);
        u64 spk = pack2(ca.y, cb.y);
#pragma unroll
        for (int mu = 0; mu < 6; mu++) {
            float4 P = sP4[w][mu * 6 + nu];
            T0p[mu] = fma2(pack2(P.x, P.x), cpk, T0p[mu]);
            T0p[mu] = fma2(pack2(P.y, P.y), spk, T0p[mu]);
            T1p[mu] = fma2(pack2(P.z, P.z), cpk, T1p[mu]);
            T1p[mu] = fma2(pack2(P.w, P.w), spk, T1p[mu]);
        }
    }

    // --- fused synthesis + activation + U accumulation (all f32x2) ---------
    const float actq = g_act * qw[y];
    const float m2actq = -2.0f * actq;
    u64 U2[12];
#pragma unroll
    for (int k = 0; k < 12; k++) U2[k] = 0ULL;
#pragma unroll 4
    for (int x = 0; x < NA; x++) {
        const ulonglong2* cp = (const ulonglong2*)strigX2[x];
        ulonglong2 c01 = cp[0], c23 = cp[1], c45 = cp[2];
        ulonglong2 c67 = cp[3], c89 = cp[4], cAB = cp[5];
        u64 g2 = 0ULL;
        g2 = fma2(c01.x, T0p[0], g2); g2 = fma2(c01.y, T1p[0], g2);
        g2 = fma2(c23.x, T0p[1], g2); g2 = fma2(c23.y, T1p[1], g2);
        g2 = fma2(c45.x, T0p[2], g2); g2 = fma2(c45.y, T1p[2], g2);
        g2 = fma2(c67.x, T0p[3], g2); g2 = fma2(c67.y, T1p[3], g2);
        g2 = fma2(c89.x, T0p[4], g2); g2 = fma2(c89.y, T1p[4], g2);
        g2 = fma2(cAB.x, T0p[5], g2); g2 = fma2(cAB.y, T1p[5], g2);
        float ga, gb;
        unpack2(g2, ga, gb);
        float ha = fmaf(m2actq, rcpa(ex2a(ga) + 1.0f), actq);
        float hb = fmaf(m2actq, rcpa(ex2a(gb) + 1.0f), actq);
        u64 h2 = pack2(ha, hb);
        U2[0]  = fma2(c01.x, h2, U2[0]);  U2[1]  = fma2(c01.y, h2, U2[1]);
        U2[2]  = fma2(c23.x, h2, U2[2]);  U2[3]  = fma2(c23.y, h2, U2[3]);
        U2[4]  = fma2(c45.x, h2, U2[4]);  U2[5]  = fma2(c45.y, h2, U2[5]);
        U2[6]  = fma2(c67.x, h2, U2[6]);  U2[7]  = fma2(c67.y, h2, U2[7]);
        U2[8]  = fma2(c89.x, h2, U2[8]);  U2[9]  = fma2(c89.y, h2, U2[9]);
        U2[10] = fma2(cAB.x, h2, U2[10]); U2[11] = fma2(cAB.y, h2, U2[11]);
    }
    {
        float U0[12], U1[12];
#pragma unroll
        for (int k = 0; k < 12; k++) unpack2(U2[k], U0[k], U1[k]);
#pragma unroll
        for (int mu = 0; mu < 6; mu++)
            sU[w][mu][z0] = make_float2(U0[2 * mu], U0[2 * mu + 1]);
        if (lane < 16) {
#pragma unroll
            for (int mu = 0; mu < 6; mu++)
                sU[w][mu][z1] = make_float2(U1[2 * mu], U1[2 * mu + 1]);
        }
    }
    __syncwarp();

    // --- Q forms part 1: forms 0..31, one per lane --------------------------
    {
        int mu = lane / 6, nu = lane % 6;
        u64 Qa = 0ULL, Qb = 0ULL;   // (Q00,Q10), (Q01,Q11)
        for (int z = 0; z < NA; z++) {
            u64 u2 = *(const u64*)&sU[w][mu][z];
            ulonglong2 cs = *(const ulonglong2*)&strigX2[z][2 * nu];
            Qa = fma2(u2, cs.x, Qa);
            Qb = fma2(u2, cs.y, Qb);
        }
        float Q00, Q10, Q01, Q11;
        unpack2(Qa, Q00, Q10);
        unpack2(Qb, Q01, Q11);
        *(float4*)(g_Q + ((size_t)(b * NB + y)) * 144 + lane * 4) =
            make_float4(Q00, Q01, Q10, Q11);
    }
    // --- Q forms part 2: forms 32..35 (mu=5, nu=2..5) over 8-lane groups ---
    {
        int grp = lane >> 3;
        int nu = 2 + grp;
        u64 Qa = 0ULL, Qb = 0ULL;
#pragma unroll
        for (int k = 0; k < 6; k++) {
            int z = (lane & 7) * 6 + k;
            u64 u2 = *(const u64*)&sU[w][5][z];
            ulonglong2 cs = *(const ulonglong2*)&strigX2[z][2 * nu];
            Qa = fma2(u2, cs.x, Qa);
            Qb = fma2(u2, cs.y, Qb);
        }
#pragma unroll
        for (int off = 1; off < 8; off <<= 1) {
            Qa = add2(Qa, __shfl_xor_sync(0xffffffffu, Qa, off));
            Qb = add2(Qb, __shfl_xor_sync(0xffffffffu, Qb, off));
        }
        if ((lane & 7) == 0) {
            float Q00, Q10, Q01, Q11;
            unpack2(Qa, Q00, Q10);
            unpack2(Qb, Q01, Q11);
            *(float4*)(g_Q + ((size_t)(b * NB + y)) * 144 + (32 + grp) * 4) =
                make_float4(Q00, Q01, Q10, Q11);
        }
    }
}

// ---------------------------------------------------------------------------
// Scatter (orbit-based): one thread computes ALL 4 outputs of a (mu,nu) orbit
// at level l, sharing the 4 B loads + 1 Q float4 per y across the outputs.
// grid (256 b, 2) x 384 threads = 48 orbit slots x 8 y-lanes (3 y each).
// 8-lane packed shuffle reduce; lane 0 writes the 1-4 distinct outputs.
// ---------------------------------------------------------------------------
__global__ __launch_bounds__(384) void scatter_kernel(const float* __restrict__ D,
                                                      float* __restrict__ out) {
    const int b = blockIdx.x;
    const int tid = threadIdx.x;
    int task = blockIdx.y * 48 + (tid >> 3);   // orbit id 0..95
    const int h = tid & 7;                     // y-eighth (3 y each)
    const bool valid = task < 91;
    if (!valid) task = 90;

    // decode orbit -> (l, mu, nu):  task = sum_{l'<l}(l'+1)^2 + mu*(l+1) + nu
    int l = 0, rem = task;
    while (rem >= (l + 1) * (l + 1)) { rem -= (l + 1) * (l + 1); l++; }
    int mu = rem / (l + 1), nu = rem % (l + 1);
    int dl = 2 * l + 1, off = c_off[l];
    int r0 = l - mu, r1 = l + mu, q0 = l - nu, q1 = l + nu;
    int i00 = off + r0 * dl + q0, i01 = off + r0 * dl + q1;
    int i10 = off + r1 * dl + q0, i11 = off + r1 * dl + q1;
    int mn4 = (mu * 6 + nu) * 4;

    float o00 = 0.f, o01 = 0.f, o10 = 0.f, o11 = 0.f;
#pragma unroll
    for (int yv = 0; yv < 3; yv++) {
        int y = h * 3 + yv;
        float4 Q = *(const float4*)(g_Q + ((size_t)(b * NB + y)) * 144 + mn4);
        const float* By = D + (size_t)y * NA * DIM;
        float B00 = By[i00], B01 = By[i01], B10 = By[i10], B11 = By[i11];
        o00 += Q.x * B00 - Q.y * B01 + Q.z * B10 - Q.w * B11;
        o01 += Q.x * B01 + Q.y * B00 + Q.z * B11 + Q.w * B10;
        o10 += Q.x * B10 - Q.y * B11 - Q.z * B00 + Q.w * B01;
        o11 += Q.x * B11 + Q.y * B10 - Q.z * B01 - Q.w * B00;
    }
    u64 Pa = pack2(o00, o01), Pb = pack2(o10, o11);
#pragma unroll
    for (int o = 1; o < 8; o <<= 1) {
        Pa = add2(Pa, __shfl_xor_sync(0xffffffffu, Pa, o));
        Pb = add2(Pb, __shfl_xor_sync(0xffffffffu, Pb, o));
    }
    if (valid && h == 0) {
        unpack2(Pa, o00, o01);
        unpack2(Pb, o10, o11);
        const float ss = sqrtf(286.f);
        float* ob = out + (size_t)b * DIM;
        ob[i00] = ss * o00;
        if (nu > 0) ob[i01] = ss * o01;
        if (mu > 0) ob[i10] = ss * o10;
        if (mu > 0 && nu > 0) ob[i11] = ss * o11;
    }
}

extern "C" void kernel_launch(void* const* d_in, const int* in_sizes, int n_in,
                              void* d_out, int out_size) {
    const float* feat = (const float*)d_in[0];  // [256, 286]
    const float* D    = (const float*)d_in[1];  // [48, 24, 48, 286]
    const float* qw   = (const float*)d_in[2];  // [24]
    float* out        = (float*)d_out;          // [256, 286]

    act_kernel<<<48, 256>>>();
    prep_kernel<<<1, 512>>>(D);
    so3_main<<<dim3(NBATCH, 6), 128>>>(feat, D, qw);
    scatter_kernel<<<dim3(NBATCH, 2), 384>>>(D, out);
}